// round 7
// baseline (speedup 1.0000x reference)
#include <cuda_runtime.h>
#include <cuda_fp16.h>
#include <cuda_bf16.h>
#include <math.h>

#define NUM_LAYERS 2
#define B_SZ 2
#define S_TOTAL 13294
#define D_MODEL 256
#define NH 8
#define DH 32
#define NL 4
#define NP 4
#define DFF 1024
#define M_TOTAL (B_SZ * S_TOTAL)

__constant__ int c_H[4]     = {100, 50, 25, 13};
__constant__ int c_W[4]     = {100, 50, 25, 13};
__constant__ int c_start[4] = {0, 10000, 12500, 13125};

// ---------------- scratch (static device globals; no allocation) -------------
__device__ __half2 g_value_h[M_TOTAL * 128];   // value in fp16, [row][128 half2]
__device__ float g_off  [M_TOTAL * D_MODEL];
__device__ float g_attn [M_TOTAL * 128];
__device__ float g_msda [M_TOTAL * D_MODEL];
__device__ float g_tmp  [M_TOTAL * D_MODEL];
__device__ float g_x    [M_TOTAL * D_MODEL];
__device__ float g_hid  [M_TOTAL * DFF];
__device__ float g_ref  [M_TOTAL * NL * 2];

// ---------------- reference points ------------------------------------------
__global__ void ref_kernel(const float* __restrict__ vr, float* __restrict__ ref)
{
    int idx = blockIdx.x * blockDim.x + threadIdx.x;
    if (idx >= B_SZ * S_TOTAL) return;
    int b = idx / S_TOTAL;
    int s = idx % S_TOTAL;

    int lvl = 0, rem = s;
    while (lvl < 3 && rem >= c_H[lvl] * c_W[lvl]) { rem -= c_H[lvl] * c_W[lvl]; lvl++; }
    int W_ = c_W[lvl], H_ = c_H[lvl];
    int i = rem / W_, j = rem % W_;

    float vrx = vr[(b * NL + lvl) * 2 + 0];
    float vry = vr[(b * NL + lvl) * 2 + 1];
    float bx = (j + 0.5f) / (vrx * (float)W_);
    float by = (i + 0.5f) / (vry * (float)H_);

    #pragma unroll
    for (int l = 0; l < NL; l++) {
        float vx = vr[(b * NL + l) * 2 + 0];
        float vy = vr[(b * NL + l) * 2 + 1];
        ref[((size_t)idx * NL + l) * 2 + 0] = bx * vx;
        ref[((size_t)idx * NL + l) * 2 + 1] = by * vy;
    }
}

// ---------------- TF32 tensor-core GEMM --------------------------------------
__device__ __forceinline__ unsigned f2tf32(float f) {
    unsigned u;
    asm("cvt.rna.tf32.f32 %0, %1;" : "=r"(u) : "f"(f));
    return u;
}

#define MMA_TF32(c0,c1,c2,c3, a0,a1,a2,a3, b0,b1) \
    asm volatile("mma.sync.aligned.m16n8k8.row.col.f32.tf32.tf32.f32 " \
        "{%0,%1,%2,%3},{%4,%5,%6,%7},{%8,%9},{%0,%1,%2,%3};" \
        : "+f"(c0), "+f"(c1), "+f"(c2), "+f"(c3) \
        : "r"(a0), "r"(a1), "r"(a2), "r"(a3), "r"(b0), "r"(b1))

#define LDK 136

// outMode: 0 = float out, 1 = float out + relu, 2 = fp16 out (to __half2*)
__global__ __launch_bounds__(256)
void gemm_tc_kernel(const float* __restrict__ A,
                    const float* __restrict__ W,
                    const float* __restrict__ bias,
                    float* __restrict__ C,
                    __half2* __restrict__ Ch,
                    int M, int N, int K, int outMode)
{
    __shared__ unsigned As[2][16][LDK];   // [buf][k][m]
    __shared__ unsigned Bs[2][16][LDK];   // [buf][k][n]

    const int bm = blockIdx.y * 128;
    const int bn = blockIdx.x * 128;
    const int tid  = threadIdx.x;
    const int lane = tid & 31;
    const int warp = tid >> 5;
    const int wm = (warp >> 2) * 64;
    const int wn = (warp & 3) * 32;

    const int arow = tid >> 1;
    const int acol = (tid & 1) * 8;
    const int brow = tid >> 4;
    const int bcol = (tid & 15) * 8;

    const int grow = lane >> 2;
    const int gk   = lane & 3;

    float c[4][4][4];
    #pragma unroll
    for (int i = 0; i < 4; i++)
        #pragma unroll
        for (int j = 0; j < 4; j++)
            #pragma unroll
            for (int r = 0; r < 4; r++) c[i][j][r] = 0.f;

    const int NT = K >> 4;
    float4 pa0, pa1, pb0, pb1;
    const bool arow_ok = (bm + arow < M);

    {
        pa0 = make_float4(0.f,0.f,0.f,0.f); pa1 = pa0;
        if (arow_ok) {
            const float* ap = A + (size_t)(bm + arow) * K + acol;
            pa0 = *(const float4*)ap;
            pa1 = *(const float4*)(ap + 4);
        }
        pb0 = *(const float4*)(W + (size_t)brow * N + bn + bcol);
        pb1 = *(const float4*)(W + (size_t)brow * N + bn + bcol + 4);

        As[0][acol+0][arow] = f2tf32(pa0.x); As[0][acol+1][arow] = f2tf32(pa0.y);
        As[0][acol+2][arow] = f2tf32(pa0.z); As[0][acol+3][arow] = f2tf32(pa0.w);
        As[0][acol+4][arow] = f2tf32(pa1.x); As[0][acol+5][arow] = f2tf32(pa1.y);
        As[0][acol+6][arow] = f2tf32(pa1.z); As[0][acol+7][arow] = f2tf32(pa1.w);
        uint4 u0 = make_uint4(f2tf32(pb0.x), f2tf32(pb0.y), f2tf32(pb0.z), f2tf32(pb0.w));
        uint4 u1 = make_uint4(f2tf32(pb1.x), f2tf32(pb1.y), f2tf32(pb1.z), f2tf32(pb1.w));
        *(uint4*)&Bs[0][brow][bcol]     = u0;
        *(uint4*)&Bs[0][brow][bcol + 4] = u1;
    }
    __syncthreads();

    for (int t = 0; t < NT; t++) {
        const int cur = t & 1;
        const int nxt = cur ^ 1;

        if (t + 1 < NT) {
            const int k0 = (t + 1) << 4;
            pa0 = make_float4(0.f,0.f,0.f,0.f); pa1 = pa0;
            if (arow_ok) {
                const float* ap = A + (size_t)(bm + arow) * K + k0 + acol;
                pa0 = *(const float4*)ap;
                pa1 = *(const float4*)(ap + 4);
            }
            pb0 = *(const float4*)(W + (size_t)(k0 + brow) * N + bn + bcol);
            pb1 = *(const float4*)(W + (size_t)(k0 + brow) * N + bn + bcol + 4);
        }

        #pragma unroll
        for (int ks = 0; ks < 2; ks++) {
            const int kb = ks * 8;
            unsigned af[4][4], bf[4][2];
            #pragma unroll
            for (int mt = 0; mt < 4; mt++) {
                int r = wm + mt * 16 + grow;
                af[mt][0] = As[cur][kb + gk    ][r];
                af[mt][1] = As[cur][kb + gk    ][r + 8];
                af[mt][2] = As[cur][kb + gk + 4][r];
                af[mt][3] = As[cur][kb + gk + 4][r + 8];
            }
            #pragma unroll
            for (int nt = 0; nt < 4; nt++) {
                int n = wn + nt * 8 + grow;
                bf[nt][0] = Bs[cur][kb + gk    ][n];
                bf[nt][1] = Bs[cur][kb + gk + 4][n];
            }
            #pragma unroll
            for (int mt = 0; mt < 4; mt++)
                #pragma unroll
                for (int nt = 0; nt < 4; nt++)
                    MMA_TF32(c[mt][nt][0], c[mt][nt][1], c[mt][nt][2], c[mt][nt][3],
                             af[mt][0], af[mt][1], af[mt][2], af[mt][3],
                             bf[nt][0], bf[nt][1]);
        }

        if (t + 1 < NT) {
            As[nxt][acol+0][arow] = f2tf32(pa0.x); As[nxt][acol+1][arow] = f2tf32(pa0.y);
            As[nxt][acol+2][arow] = f2tf32(pa0.z); As[nxt][acol+3][arow] = f2tf32(pa0.w);
            As[nxt][acol+4][arow] = f2tf32(pa1.x); As[nxt][acol+5][arow] = f2tf32(pa1.y);
            As[nxt][acol+6][arow] = f2tf32(pa1.z); As[nxt][acol+7][arow] = f2tf32(pa1.w);
            uint4 u0 = make_uint4(f2tf32(pb0.x), f2tf32(pb0.y), f2tf32(pb0.z), f2tf32(pb0.w));
            uint4 u1 = make_uint4(f2tf32(pb1.x), f2tf32(pb1.y), f2tf32(pb1.z), f2tf32(pb1.w));
            *(uint4*)&Bs[nxt][brow][bcol]     = u0;
            *(uint4*)&Bs[nxt][brow][bcol + 4] = u1;
        }
        __syncthreads();
    }

    #pragma unroll
    for (int mt = 0; mt < 4; mt++) {
        int row0 = bm + wm + mt * 16 + grow;
        #pragma unroll
        for (int nt = 0; nt < 4; nt++) {
            int gn = bn + wn + nt * 8 + (lane & 3) * 2;
            float b0 = bias[gn], b1 = bias[gn + 1];
            float v0 = c[mt][nt][0] + b0;
            float v1 = c[mt][nt][1] + b1;
            float v2 = c[mt][nt][2] + b0;
            float v3 = c[mt][nt][3] + b1;
            if (outMode == 1) {
                v0 = fmaxf(v0, 0.f); v1 = fmaxf(v1, 0.f);
                v2 = fmaxf(v2, 0.f); v3 = fmaxf(v3, 0.f);
            }
            if (outMode == 2) {
                if (row0 < M)
                    Ch[((size_t)row0 * N + gn) >> 1] = __floats2half2_rn(v0, v1);
                if (row0 + 8 < M)
                    Ch[((size_t)(row0 + 8) * N + gn) >> 1] = __floats2half2_rn(v2, v3);
            } else {
                if (row0 < M)
                    *(float2*)(C + (size_t)row0 * N + gn) = make_float2(v0, v1);
                if (row0 + 8 < M)
                    *(float2*)(C + (size_t)(row0 + 8) * N + gn) = make_float2(v2, v3);
            }
        }
    }
}

// ---------------- MSDA v3b: fp16 value, 2 heads per warp (fixed shuffle) -----
// lane = hh*16 + ch2 ; hh = head-in-pair, ch2 = channel-pair (covers 2 channels)
__global__ __launch_bounds__(256)
void msda_h_kernel(const __half2* __restrict__ value,
                   const float* __restrict__ off,
                   const float* __restrict__ attn_logits,
                   const float* __restrict__ ref,
                   float* __restrict__ out)
{
    constexpr int kH[4]  = {100, 50, 25, 13};
    constexpr int kW[4]  = {100, 50, 25, 13};
    constexpr int kSt[4] = {0, 10000, 12500, 13125};

    int gwarp = (blockIdx.x * blockDim.x + threadIdx.x) >> 5;
    int lane  = threadIdx.x & 31;
    const int NUNITS = B_SZ * S_TOTAL * 4;     // (bq, head-pair)
    if (gwarp >= NUNITS) return;

    int hp = gwarp & 3;
    int bq = gwarp >> 2;
    int b  = (bq >= S_TOTAL) ? 1 : 0;
    int hh  = lane >> 4;      // 0/1: head within pair
    int ch2 = lane & 15;      // channel-pair index (channels 2*ch2, 2*ch2+1)
    int h   = hp * 2 + hh;

    // offsets: lane's float2 = (x,y) of sample point ch2 for head h
    float2 offv = __ldg((const float2*)(off + (size_t)bq * 256 + h * 32) + ch2);

    // softmax over 16 logits within each 16-lane half
    float v = __ldg(attn_logits + (size_t)bq * 128 + h * 16 + ch2);
    float m = v;
    #pragma unroll
    for (int o = 8; o > 0; o >>= 1) m = fmaxf(m, __shfl_xor_sync(0xffffffffu, m, o));
    float e = __expf(v - m);
    float ssum = e;
    #pragma unroll
    for (int o = 8; o > 0; o >>= 1) ssum += __shfl_xor_sync(0xffffffffu, ssum, o);
    float aw = e / ssum;   // weight for sample index == ch2 (per head-half)

    const float* refp = ref + (size_t)bq * (NL * 2);

    float accx = 0.f, accy = 0.f;
    #pragma unroll
    for (int l = 0; l < NL; l++) {
        const int H_ = kH[l], W_ = kW[l];
        const float fW = (float)W_, fH = (float)H_;
        const float invW = 1.f / fW, invH = 1.f / fH;
        float refx = __ldg(refp + l * 2 + 0);
        float refy = __ldg(refp + l * 2 + 1);
        // half2 row stride between spatial positions = NH*16 = 128
        const __half2* vbase = value + ((size_t)(b * S_TOTAL + kSt[l]) * NH + h) * 16 + ch2;

        #pragma unroll
        for (int p = 0; p < NP; p++) {
            const int idx16 = l * NP + p;          // sample index 0..15
            const int src = hh * 16 + idx16;       // lane holding this sample's data
            float w16 = __shfl_sync(0xffffffffu, aw, src);
            float ox  = __shfl_sync(0xffffffffu, offv.x, src);
            float oy  = __shfl_sync(0xffffffffu, offv.y, src);

            float x = (refx + ox * invW) * fW - 0.5f;
            float y = (refy + oy * invH) * fH - 0.5f;
            float x0f = floorf(x), y0f = floorf(y);
            int x0 = (int)x0f, y0 = (int)y0f;
            float fx = x - x0f, fy = y - y0f;

            float mx0 = ((unsigned)x0     < (unsigned)W_) ? 1.f : 0.f;
            float mx1 = ((unsigned)(x0+1) < (unsigned)W_) ? 1.f : 0.f;
            float my0 = ((unsigned)y0     < (unsigned)H_) ? 1.f : 0.f;
            float my1 = ((unsigned)(y0+1) < (unsigned)H_) ? 1.f : 0.f;

            float gx1 = fx * mx1, gx0 = (1.f - fx) * mx0;
            float gy1 = fy * my1, gy0 = (1.f - fy) * my0;
            float w00 = gx0 * gy0, w10 = gx1 * gy0;
            float w01 = gx0 * gy1, w11 = gx1 * gy1;

            int cx0 = min(max(x0, 0), W_ - 1);
            int cx1 = min(max(x0 + 1, 0), W_ - 1);
            int cy0 = min(max(y0, 0), H_ - 1);
            int cy1 = min(max(y0 + 1, 0), H_ - 1);
            int r0 = cy0 * W_, r1 = cy1 * W_;

            __half2 h00 = __ldg(vbase + (size_t)(r0 + cx0) * 128);
            __half2 h10 = __ldg(vbase + (size_t)(r0 + cx1) * 128);
            __half2 h01 = __ldg(vbase + (size_t)(r1 + cx0) * 128);
            __half2 h11 = __ldg(vbase + (size_t)(r1 + cx1) * 128);

            float2 f00 = __half22float2(h00);
            float2 f10 = __half22float2(h10);
            float2 f01 = __half22float2(h01);
            float2 f11 = __half22float2(h11);

            float sx = fmaf(w00, f00.x, fmaf(w10, f10.x, fmaf(w01, f01.x, w11 * f11.x)));
            float sy = fmaf(w00, f00.y, fmaf(w10, f10.y, fmaf(w01, f01.y, w11 * f11.y)));
            accx = fmaf(w16, sx, accx);
            accy = fmaf(w16, sy, accy);
        }
    }
    *(float2*)(out + ((size_t)bq * NH + h) * DH + 2 * ch2) = make_float2(accx, accy);
}

// ---------------- residual add + LayerNorm (one block per row, 256 thr) -----
__global__ void add_ln_kernel(const float* __restrict__ xin,
                              const float* __restrict__ r,
                              const float* __restrict__ g,
                              const float* __restrict__ bt,
                              float* __restrict__ xout)
{
    int row = blockIdx.x;
    int t = threadIdx.x;
    float v = xin[(size_t)row * 256 + t] + r[(size_t)row * 256 + t];

    float s1 = v, s2 = v * v;
    #pragma unroll
    for (int o = 16; o > 0; o >>= 1) {
        s1 += __shfl_xor_sync(0xffffffffu, s1, o);
        s2 += __shfl_xor_sync(0xffffffffu, s2, o);
    }
    __shared__ float sh1[8], sh2[8];
    int w = t >> 5, lane = t & 31;
    if (lane == 0) { sh1[w] = s1; sh2[w] = s2; }
    __syncthreads();
    if (w == 0) {
        s1 = (lane < 8) ? sh1[lane] : 0.f;
        s2 = (lane < 8) ? sh2[lane] : 0.f;
        #pragma unroll
        for (int o = 4; o > 0; o >>= 1) {
            s1 += __shfl_xor_sync(0xffffffffu, s1, o);
            s2 += __shfl_xor_sync(0xffffffffu, s2, o);
        }
        if (lane == 0) { sh1[0] = s1; sh2[0] = s2; }
    }
    __syncthreads();
    float mean = sh1[0] * (1.f / 256.f);
    float var  = sh2[0] * (1.f / 256.f) - mean * mean;
    float inv  = rsqrtf(var + 1e-5f);
    xout[(size_t)row * 256 + t] = (v - mean) * inv * g[t] + bt[t];
}

// -----------------------------------------------------------------------------
extern "C" void kernel_launch(void* const* d_in, const int* in_sizes, int n_in,
                              void* d_out, int out_size)
{
    const float* src    = (const float*)d_in[0];
    const float* vr     = (const float*)d_in[2];
    const float* W_off  = (const float*)d_in[3];
    const float* b_off  = (const float*)d_in[4];
    const float* W_attn = (const float*)d_in[5];
    const float* b_attn = (const float*)d_in[6];
    const float* W_val  = (const float*)d_in[7];
    const float* b_val  = (const float*)d_in[8];
    const float* W_out  = (const float*)d_in[9];
    const float* b_out  = (const float*)d_in[10];
    const float* ln1_g  = (const float*)d_in[11];
    const float* ln1_b  = (const float*)d_in[12];
    const float* W1     = (const float*)d_in[13];
    const float* b1     = (const float*)d_in[14];
    const float* W2     = (const float*)d_in[15];
    const float* b2     = (const float*)d_in[16];
    const float* ln2_g  = (const float*)d_in[17];
    const float* ln2_b  = (const float*)d_in[18];

    __half2* valueh;
    float *off, *attn, *msda, *tmp, *xb, *hid, *refp;
    cudaGetSymbolAddress((void**)&valueh, g_value_h);
    cudaGetSymbolAddress((void**)&off,   g_off);
    cudaGetSymbolAddress((void**)&attn,  g_attn);
    cudaGetSymbolAddress((void**)&msda,  g_msda);
    cudaGetSymbolAddress((void**)&tmp,   g_tmp);
    cudaGetSymbolAddress((void**)&xb,    g_x);
    cudaGetSymbolAddress((void**)&hid,   g_hid);
    cudaGetSymbolAddress((void**)&refp,  g_ref);

    const int M = M_TOTAL;
    const int GM = (M + 127) / 128;   // 208

    ref_kernel<<<(M + 255) / 256, 256>>>(vr, refp);

    for (int i = 0; i < NUM_LAYERS; i++) {
        const float* xin = (i == 0) ? src : xb;

        gemm_tc_kernel<<<dim3(2, GM), 256>>>(xin, W_val + (size_t)i * 256 * 256,
                                             b_val + i * 256, nullptr, valueh, M, 256, 256, 2);
        gemm_tc_kernel<<<dim3(2, GM), 256>>>(xin, W_off + (size_t)i * 256 * 256,
                                             b_off + i * 256, off, nullptr, M, 256, 256, 0);
        gemm_tc_kernel<<<dim3(1, GM), 256>>>(xin, W_attn + (size_t)i * 256 * 128,
                                             b_attn + i * 128, attn, nullptr, M, 128, 256, 0);

        int nunits = B_SZ * S_TOTAL * 4;
        msda_h_kernel<<<(nunits * 32 + 255) / 256, 256>>>(valueh, off, attn, refp, msda);

        gemm_tc_kernel<<<dim3(2, GM), 256>>>(msda, W_out + (size_t)i * 256 * 256,
                                             b_out + i * 256, tmp, nullptr, M, 256, 256, 0);
        add_ln_kernel<<<M, 256>>>(xin, tmp, ln1_g + i * 256, ln1_b + i * 256, xb);

        gemm_tc_kernel<<<dim3(8, GM), 256>>>(xb, W1 + (size_t)i * 256 * 1024,
                                             b1 + i * 1024, hid, nullptr, M, 1024, 256, 1);
        gemm_tc_kernel<<<dim3(2, GM), 256>>>(hid, W2 + (size_t)i * 1024 * 256,
                                             b2 + i * 256, tmp, nullptr, M, 256, 1024, 0);

        float* lnout = (i == NUM_LAYERS - 1) ? (float*)d_out : xb;
        add_ln_kernel<<<M, 256>>>(xb, tmp, ln2_g + i * 256, ln2_b + i * 256, lnout);
    }
}

// round 8
// speedup vs baseline: 1.5495x; 1.5495x over previous
#include <cuda_runtime.h>
#include <cuda_fp16.h>
#include <cuda_bf16.h>
#include <math.h>

#define NUM_LAYERS 2
#define B_SZ 2
#define S_TOTAL 13294
#define D_MODEL 256
#define NH 8
#define DH 32
#define NL 4
#define NP 4
#define DFF 1024
#define M_TOTAL (B_SZ * S_TOTAL)

__constant__ int c_H[4]     = {100, 50, 25, 13};
__constant__ int c_W[4]     = {100, 50, 25, 13};
__constant__ int c_start[4] = {0, 10000, 12500, 13125};

// ---------------- scratch (static device globals; no allocation) -------------
__device__ __half2 g_value_h[M_TOTAL * 128];   // value in fp16, [row][128 half2]
__device__ float g_off  [M_TOTAL * D_MODEL];
__device__ float g_attn [M_TOTAL * 128];
__device__ float g_msda [M_TOTAL * D_MODEL];
__device__ float g_tmp  [M_TOTAL * D_MODEL];
__device__ float g_x    [M_TOTAL * D_MODEL];
__device__ float g_hid  [M_TOTAL * DFF];
__device__ float g_ref  [M_TOTAL * NL * 2];

// ---------------- reference points ------------------------------------------
__global__ void ref_kernel(const float* __restrict__ vr, float* __restrict__ ref)
{
    int idx = blockIdx.x * blockDim.x + threadIdx.x;
    if (idx >= B_SZ * S_TOTAL) return;
    int b = idx / S_TOTAL;
    int s = idx % S_TOTAL;

    int lvl = 0, rem = s;
    while (lvl < 3 && rem >= c_H[lvl] * c_W[lvl]) { rem -= c_H[lvl] * c_W[lvl]; lvl++; }
    int W_ = c_W[lvl], H_ = c_H[lvl];
    int i = rem / W_, j = rem % W_;

    float vrx = vr[(b * NL + lvl) * 2 + 0];
    float vry = vr[(b * NL + lvl) * 2 + 1];
    float bx = (j + 0.5f) / (vrx * (float)W_);
    float by = (i + 0.5f) / (vry * (float)H_);

    #pragma unroll
    for (int l = 0; l < NL; l++) {
        float vx = vr[(b * NL + l) * 2 + 0];
        float vy = vr[(b * NL + l) * 2 + 1];
        ref[((size_t)idx * NL + l) * 2 + 0] = bx * vx;
        ref[((size_t)idx * NL + l) * 2 + 1] = by * vy;
    }
}

// ---------------- TF32 tensor-core GEMM (compile-time epilogue mode) ---------
__device__ __forceinline__ unsigned f2tf32(float f) {
    unsigned u;
    asm("cvt.rna.tf32.f32 %0, %1;" : "=r"(u) : "f"(f));
    return u;
}

#define MMA_TF32(c0,c1,c2,c3, a0,a1,a2,a3, b0,b1) \
    asm volatile("mma.sync.aligned.m16n8k8.row.col.f32.tf32.tf32.f32 " \
        "{%0,%1,%2,%3},{%4,%5,%6,%7},{%8,%9},{%0,%1,%2,%3};" \
        : "+f"(c0), "+f"(c1), "+f"(c2), "+f"(c3) \
        : "r"(a0), "r"(a1), "r"(a2), "r"(a3), "r"(b0), "r"(b1))

#define LDK 136

// OUTMODE: 0 = float out, 1 = float out + relu, 2 = fp16 out (to __half2*)
template<int OUTMODE>
__global__ __launch_bounds__(256)
void gemm_tc_kernel(const float* __restrict__ A,
                    const float* __restrict__ W,
                    const float* __restrict__ bias,
                    float* __restrict__ C,
                    __half2* __restrict__ Ch,
                    int M, int N, int K)
{
    __shared__ unsigned As[2][16][LDK];   // [buf][k][m]
    __shared__ unsigned Bs[2][16][LDK];   // [buf][k][n]

    const int bm = blockIdx.y * 128;
    const int bn = blockIdx.x * 128;
    const int tid  = threadIdx.x;
    const int lane = tid & 31;
    const int warp = tid >> 5;
    const int wm = (warp >> 2) * 64;
    const int wn = (warp & 3) * 32;

    const int arow = tid >> 1;
    const int acol = (tid & 1) * 8;
    const int brow = tid >> 4;
    const int bcol = (tid & 15) * 8;

    const int grow = lane >> 2;
    const int gk   = lane & 3;

    float c[4][4][4];
    #pragma unroll
    for (int i = 0; i < 4; i++)
        #pragma unroll
        for (int j = 0; j < 4; j++)
            #pragma unroll
            for (int r = 0; r < 4; r++) c[i][j][r] = 0.f;

    const int NT = K >> 4;
    float4 pa0, pa1, pb0, pb1;
    const bool arow_ok = (bm + arow < M);

    {
        pa0 = make_float4(0.f,0.f,0.f,0.f); pa1 = pa0;
        if (arow_ok) {
            const float* ap = A + (size_t)(bm + arow) * K + acol;
            pa0 = *(const float4*)ap;
            pa1 = *(const float4*)(ap + 4);
        }
        pb0 = *(const float4*)(W + (size_t)brow * N + bn + bcol);
        pb1 = *(const float4*)(W + (size_t)brow * N + bn + bcol + 4);

        As[0][acol+0][arow] = f2tf32(pa0.x); As[0][acol+1][arow] = f2tf32(pa0.y);
        As[0][acol+2][arow] = f2tf32(pa0.z); As[0][acol+3][arow] = f2tf32(pa0.w);
        As[0][acol+4][arow] = f2tf32(pa1.x); As[0][acol+5][arow] = f2tf32(pa1.y);
        As[0][acol+6][arow] = f2tf32(pa1.z); As[0][acol+7][arow] = f2tf32(pa1.w);
        uint4 u0 = make_uint4(f2tf32(pb0.x), f2tf32(pb0.y), f2tf32(pb0.z), f2tf32(pb0.w));
        uint4 u1 = make_uint4(f2tf32(pb1.x), f2tf32(pb1.y), f2tf32(pb1.z), f2tf32(pb1.w));
        *(uint4*)&Bs[0][brow][bcol]     = u0;
        *(uint4*)&Bs[0][brow][bcol + 4] = u1;
    }
    __syncthreads();

    for (int t = 0; t < NT; t++) {
        const int cur = t & 1;
        const int nxt = cur ^ 1;

        if (t + 1 < NT) {
            const int k0 = (t + 1) << 4;
            pa0 = make_float4(0.f,0.f,0.f,0.f); pa1 = pa0;
            if (arow_ok) {
                const float* ap = A + (size_t)(bm + arow) * K + k0 + acol;
                pa0 = *(const float4*)ap;
                pa1 = *(const float4*)(ap + 4);
            }
            pb0 = *(const float4*)(W + (size_t)(k0 + brow) * N + bn + bcol);
            pb1 = *(const float4*)(W + (size_t)(k0 + brow) * N + bn + bcol + 4);
        }

        #pragma unroll
        for (int ks = 0; ks < 2; ks++) {
            const int kb = ks * 8;
            unsigned af[4][4], bf[4][2];
            #pragma unroll
            for (int mt = 0; mt < 4; mt++) {
                int r = wm + mt * 16 + grow;
                af[mt][0] = As[cur][kb + gk    ][r];
                af[mt][1] = As[cur][kb + gk    ][r + 8];
                af[mt][2] = As[cur][kb + gk + 4][r];
                af[mt][3] = As[cur][kb + gk + 4][r + 8];
            }
            #pragma unroll
            for (int nt = 0; nt < 4; nt++) {
                int n = wn + nt * 8 + grow;
                bf[nt][0] = Bs[cur][kb + gk    ][n];
                bf[nt][1] = Bs[cur][kb + gk + 4][n];
            }
            #pragma unroll
            for (int mt = 0; mt < 4; mt++)
                #pragma unroll
                for (int nt = 0; nt < 4; nt++)
                    MMA_TF32(c[mt][nt][0], c[mt][nt][1], c[mt][nt][2], c[mt][nt][3],
                             af[mt][0], af[mt][1], af[mt][2], af[mt][3],
                             bf[nt][0], bf[nt][1]);
        }

        if (t + 1 < NT) {
            As[nxt][acol+0][arow] = f2tf32(pa0.x); As[nxt][acol+1][arow] = f2tf32(pa0.y);
            As[nxt][acol+2][arow] = f2tf32(pa0.z); As[nxt][acol+3][arow] = f2tf32(pa0.w);
            As[nxt][acol+4][arow] = f2tf32(pa1.x); As[nxt][acol+5][arow] = f2tf32(pa1.y);
            As[nxt][acol+6][arow] = f2tf32(pa1.z); As[nxt][acol+7][arow] = f2tf32(pa1.w);
            uint4 u0 = make_uint4(f2tf32(pb0.x), f2tf32(pb0.y), f2tf32(pb0.z), f2tf32(pb0.w));
            uint4 u1 = make_uint4(f2tf32(pb1.x), f2tf32(pb1.y), f2tf32(pb1.z), f2tf32(pb1.w));
            *(uint4*)&Bs[nxt][brow][bcol]     = u0;
            *(uint4*)&Bs[nxt][brow][bcol + 4] = u1;
        }
        __syncthreads();
    }

    #pragma unroll
    for (int mt = 0; mt < 4; mt++) {
        int row0 = bm + wm + mt * 16 + grow;
        #pragma unroll
        for (int nt = 0; nt < 4; nt++) {
            int gn = bn + wn + nt * 8 + (lane & 3) * 2;
            float b0 = bias[gn], b1 = bias[gn + 1];
            float v0 = c[mt][nt][0] + b0;
            float v1 = c[mt][nt][1] + b1;
            float v2 = c[mt][nt][2] + b0;
            float v3 = c[mt][nt][3] + b1;
            if (OUTMODE == 1) {
                v0 = fmaxf(v0, 0.f); v1 = fmaxf(v1, 0.f);
                v2 = fmaxf(v2, 0.f); v3 = fmaxf(v3, 0.f);
            }
            if (OUTMODE == 2) {
                if (row0 < M)
                    Ch[((size_t)row0 * N + gn) >> 1] = __floats2half2_rn(v0, v1);
                if (row0 + 8 < M)
                    Ch[((size_t)(row0 + 8) * N + gn) >> 1] = __floats2half2_rn(v2, v3);
            } else {
                if (row0 < M)
                    *(float2*)(C + (size_t)row0 * N + gn) = make_float2(v0, v1);
                if (row0 + 8 < M)
                    *(float2*)(C + (size_t)(row0 + 8) * N + gn) = make_float2(v2, v3);
            }
        }
    }
}

// ---------------- MSDA: fp16 value, 2 heads per warp -------------------------
// lane = hh*16 + ch2 ; hh = head-in-pair, ch2 = channel-pair (covers 2 channels)
__global__ __launch_bounds__(256)
void msda_h_kernel(const __half2* __restrict__ value,
                   const float* __restrict__ off,
                   const float* __restrict__ attn_logits,
                   const float* __restrict__ ref,
                   float* __restrict__ out)
{
    constexpr int kH[4]  = {100, 50, 25, 13};
    constexpr int kW[4]  = {100, 50, 25, 13};
    constexpr int kSt[4] = {0, 10000, 12500, 13125};

    int gwarp = (blockIdx.x * blockDim.x + threadIdx.x) >> 5;
    int lane  = threadIdx.x & 31;
    const int NUNITS = B_SZ * S_TOTAL * 4;     // (bq, head-pair)
    if (gwarp >= NUNITS) return;

    int hp = gwarp & 3;
    int bq = gwarp >> 2;
    int b  = (bq >= S_TOTAL) ? 1 : 0;
    int hh  = lane >> 4;      // 0/1: head within pair
    int ch2 = lane & 15;      // channel-pair index (channels 2*ch2, 2*ch2+1)
    int h   = hp * 2 + hh;

    // offsets: lane's float2 = (x,y) of sample point ch2 for head h
    float2 offv = __ldg((const float2*)(off + (size_t)bq * 256 + h * 32) + ch2);

    // softmax over 16 logits within each 16-lane half
    float v = __ldg(attn_logits + (size_t)bq * 128 + h * 16 + ch2);
    float m = v;
    #pragma unroll
    for (int o = 8; o > 0; o >>= 1) m = fmaxf(m, __shfl_xor_sync(0xffffffffu, m, o));
    float e = __expf(v - m);
    float ssum = e;
    #pragma unroll
    for (int o = 8; o > 0; o >>= 1) ssum += __shfl_xor_sync(0xffffffffu, ssum, o);
    float aw = e / ssum;   // weight for sample index == ch2 (per head-half)

    const float* refp = ref + (size_t)bq * (NL * 2);

    float accx = 0.f, accy = 0.f;
    #pragma unroll
    for (int l = 0; l < NL; l++) {
        const int H_ = kH[l], W_ = kW[l];
        const float fW = (float)W_, fH = (float)H_;
        const float invW = 1.f / fW, invH = 1.f / fH;
        float refx = __ldg(refp + l * 2 + 0);
        float refy = __ldg(refp + l * 2 + 1);
        // half2 row stride between spatial positions = NH*16 = 128
        const __half2* vbase = value + ((size_t)(b * S_TOTAL + kSt[l]) * NH + h) * 16 + ch2;

        #pragma unroll
        for (int p = 0; p < NP; p++) {
            const int idx16 = l * NP + p;          // sample index 0..15
            const int src = hh * 16 + idx16;       // lane holding this sample's data
            float w16 = __shfl_sync(0xffffffffu, aw, src);
            float ox  = __shfl_sync(0xffffffffu, offv.x, src);
            float oy  = __shfl_sync(0xffffffffu, offv.y, src);

            float x = (refx + ox * invW) * fW - 0.5f;
            float y = (refy + oy * invH) * fH - 0.5f;
            float x0f = floorf(x), y0f = floorf(y);
            int x0 = (int)x0f, y0 = (int)y0f;
            float fx = x - x0f, fy = y - y0f;

            float mx0 = ((unsigned)x0     < (unsigned)W_) ? 1.f : 0.f;
            float mx1 = ((unsigned)(x0+1) < (unsigned)W_) ? 1.f : 0.f;
            float my0 = ((unsigned)y0     < (unsigned)H_) ? 1.f : 0.f;
            float my1 = ((unsigned)(y0+1) < (unsigned)H_) ? 1.f : 0.f;

            float gx1 = fx * mx1, gx0 = (1.f - fx) * mx0;
            float gy1 = fy * my1, gy0 = (1.f - fy) * my0;
            float w00 = gx0 * gy0, w10 = gx1 * gy0;
            float w01 = gx0 * gy1, w11 = gx1 * gy1;

            int cx0 = min(max(x0, 0), W_ - 1);
            int cx1 = min(max(x0 + 1, 0), W_ - 1);
            int cy0 = min(max(y0, 0), H_ - 1);
            int cy1 = min(max(y0 + 1, 0), H_ - 1);
            int r0 = cy0 * W_, r1 = cy1 * W_;

            __half2 h00 = __ldg(vbase + (size_t)(r0 + cx0) * 128);
            __half2 h10 = __ldg(vbase + (size_t)(r0 + cx1) * 128);
            __half2 h01 = __ldg(vbase + (size_t)(r1 + cx0) * 128);
            __half2 h11 = __ldg(vbase + (size_t)(r1 + cx1) * 128);

            float2 f00 = __half22float2(h00);
            float2 f10 = __half22float2(h10);
            float2 f01 = __half22float2(h01);
            float2 f11 = __half22float2(h11);

            float sx = fmaf(w00, f00.x, fmaf(w10, f10.x, fmaf(w01, f01.x, w11 * f11.x)));
            float sy = fmaf(w00, f00.y, fmaf(w10, f10.y, fmaf(w01, f01.y, w11 * f11.y)));
            accx = fmaf(w16, sx, accx);
            accy = fmaf(w16, sy, accy);
        }
    }
    *(float2*)(out + ((size_t)bq * NH + h) * DH + 2 * ch2) = make_float2(accx, accy);
}

// ---------------- residual add + LayerNorm (one block per row, 256 thr) -----
__global__ void add_ln_kernel(const float* __restrict__ xin,
                              const float* __restrict__ r,
                              const float* __restrict__ g,
                              const float* __restrict__ bt,
                              float* __restrict__ xout)
{
    int row = blockIdx.x;
    int t = threadIdx.x;
    float v = xin[(size_t)row * 256 + t] + r[(size_t)row * 256 + t];

    float s1 = v, s2 = v * v;
    #pragma unroll
    for (int o = 16; o > 0; o >>= 1) {
        s1 += __shfl_xor_sync(0xffffffffu, s1, o);
        s2 += __shfl_xor_sync(0xffffffffu, s2, o);
    }
    __shared__ float sh1[8], sh2[8];
    int w = t >> 5, lane = t & 31;
    if (lane == 0) { sh1[w] = s1; sh2[w] = s2; }
    __syncthreads();
    if (w == 0) {
        s1 = (lane < 8) ? sh1[lane] : 0.f;
        s2 = (lane < 8) ? sh2[lane] : 0.f;
        #pragma unroll
        for (int o = 4; o > 0; o >>= 1) {
            s1 += __shfl_xor_sync(0xffffffffu, s1, o);
            s2 += __shfl_xor_sync(0xffffffffu, s2, o);
        }
        if (lane == 0) { sh1[0] = s1; sh2[0] = s2; }
    }
    __syncthreads();
    float mean = sh1[0] * (1.f / 256.f);
    float var  = sh2[0] * (1.f / 256.f) - mean * mean;
    float inv  = rsqrtf(var + 1e-5f);
    xout[(size_t)row * 256 + t] = (v - mean) * inv * g[t] + bt[t];
}

// -----------------------------------------------------------------------------
extern "C" void kernel_launch(void* const* d_in, const int* in_sizes, int n_in,
                              void* d_out, int out_size)
{
    const float* src    = (const float*)d_in[0];
    const float* vr     = (const float*)d_in[2];
    const float* W_off  = (const float*)d_in[3];
    const float* b_off  = (const float*)d_in[4];
    const float* W_attn = (const float*)d_in[5];
    const float* b_attn = (const float*)d_in[6];
    const float* W_val  = (const float*)d_in[7];
    const float* b_val  = (const float*)d_in[8];
    const float* W_out  = (const float*)d_in[9];
    const float* b_out  = (const float*)d_in[10];
    const float* ln1_g  = (const float*)d_in[11];
    const float* ln1_b  = (const float*)d_in[12];
    const float* W1     = (const float*)d_in[13];
    const float* b1     = (const float*)d_in[14];
    const float* W2     = (const float*)d_in[15];
    const float* b2     = (const float*)d_in[16];
    const float* ln2_g  = (const float*)d_in[17];
    const float* ln2_b  = (const float*)d_in[18];

    __half2* valueh;
    float *off, *attn, *msda, *tmp, *xb, *hid, *refp;
    cudaGetSymbolAddress((void**)&valueh, g_value_h);
    cudaGetSymbolAddress((void**)&off,   g_off);
    cudaGetSymbolAddress((void**)&attn,  g_attn);
    cudaGetSymbolAddress((void**)&msda,  g_msda);
    cudaGetSymbolAddress((void**)&tmp,   g_tmp);
    cudaGetSymbolAddress((void**)&xb,    g_x);
    cudaGetSymbolAddress((void**)&hid,   g_hid);
    cudaGetSymbolAddress((void**)&refp,  g_ref);

    const int M = M_TOTAL;
    const int GM = (M + 127) / 128;   // 208

    ref_kernel<<<(M + 255) / 256, 256>>>(vr, refp);

    for (int i = 0; i < NUM_LAYERS; i++) {
        const float* xin = (i == 0) ? src : xb;

        gemm_tc_kernel<2><<<dim3(2, GM), 256>>>(xin, W_val + (size_t)i * 256 * 256,
                                                b_val + i * 256, nullptr, valueh, M, 256, 256);
        gemm_tc_kernel<0><<<dim3(2, GM), 256>>>(xin, W_off + (size_t)i * 256 * 256,
                                                b_off + i * 256, off, nullptr, M, 256, 256);
        gemm_tc_kernel<0><<<dim3(1, GM), 256>>>(xin, W_attn + (size_t)i * 256 * 128,
                                                b_attn + i * 128, attn, nullptr, M, 128, 256);

        int nunits = B_SZ * S_TOTAL * 4;
        msda_h_kernel<<<(nunits * 32 + 255) / 256, 256>>>(valueh, off, attn, refp, msda);

        gemm_tc_kernel<0><<<dim3(2, GM), 256>>>(msda, W_out + (size_t)i * 256 * 256,
                                                b_out + i * 256, tmp, nullptr, M, 256, 256);
        add_ln_kernel<<<M, 256>>>(xin, tmp, ln1_g + i * 256, ln1_b + i * 256, xb);

        gemm_tc_kernel<1><<<dim3(8, GM), 256>>>(xb, W1 + (size_t)i * 256 * 1024,
                                                b1 + i * 1024, hid, nullptr, M, 1024, 256);
        gemm_tc_kernel<0><<<dim3(2, GM), 256>>>(hid, W2 + (size_t)i * 1024 * 256,
                                                b2 + i * 256, tmp, nullptr, M, 256, 1024);

        float* lnout = (i == NUM_LAYERS - 1) ? (float*)d_out : xb;
        add_ln_kernel<<<M, 256>>>(xb, tmp, ln2_g + i * 256, ln2_b + i * 256, lnout);
    }
}

// round 9
// speedup vs baseline: 1.8299x; 1.1810x over previous
#include <cuda_runtime.h>
#include <cuda_fp16.h>
#include <cuda_bf16.h>
#include <math.h>

#define NUM_LAYERS 2
#define B_SZ 2
#define S_TOTAL 13294
#define D_MODEL 256
#define NH 8
#define DH 32
#define NL 4
#define NP 4
#define DFF 1024
#define M_TOTAL (B_SZ * S_TOTAL)

__constant__ int c_H[4]     = {100, 50, 25, 13};
__constant__ int c_W[4]     = {100, 50, 25, 13};
__constant__ int c_start[4] = {0, 10000, 12500, 13125};

// ---------------- scratch (static device globals; no allocation) -------------
__device__ __half2 g_value_h[M_TOTAL * 128];   // value in fp16, [row][128 half2]
__device__ float g_off  [M_TOTAL * D_MODEL];
__device__ float g_attn [M_TOTAL * 128];
__device__ float g_msda [M_TOTAL * D_MODEL];
__device__ float g_tmp  [M_TOTAL * D_MODEL];
__device__ float g_x    [M_TOTAL * D_MODEL];
__device__ float g_hid  [M_TOTAL * DFF];
__device__ float g_ref  [M_TOTAL * NL * 2];

// ---------------- reference points ------------------------------------------
__global__ void ref_kernel(const float* __restrict__ vr, float* __restrict__ ref)
{
    int idx = blockIdx.x * blockDim.x + threadIdx.x;
    if (idx >= B_SZ * S_TOTAL) return;
    int b = idx / S_TOTAL;
    int s = idx % S_TOTAL;

    int lvl = 0, rem = s;
    while (lvl < 3 && rem >= c_H[lvl] * c_W[lvl]) { rem -= c_H[lvl] * c_W[lvl]; lvl++; }
    int W_ = c_W[lvl], H_ = c_H[lvl];
    int i = rem / W_, j = rem % W_;

    float vrx = vr[(b * NL + lvl) * 2 + 0];
    float vry = vr[(b * NL + lvl) * 2 + 1];
    float bx = (j + 0.5f) / (vrx * (float)W_);
    float by = (i + 0.5f) / (vry * (float)H_);

    #pragma unroll
    for (int l = 0; l < NL; l++) {
        float vx = vr[(b * NL + l) * 2 + 0];
        float vy = vr[(b * NL + l) * 2 + 1];
        ref[((size_t)idx * NL + l) * 2 + 0] = bx * vx;
        ref[((size_t)idx * NL + l) * 2 + 1] = by * vy;
    }
}

// ---------------- FP16 tensor-core GEMM (ldmatrix + m16n8k16) ----------------
// C[M,N] = A[M,K] @ W[K,N] + bias ; A,W converted fp32->fp16 on the fly.
// BM=BN=128, BK=32, 256 threads = 8 warps (2Mx4N), warp tile 64x32.

#define LDSM_X4(r0,r1,r2,r3,addr) \
    asm volatile("ldmatrix.sync.aligned.m8n8.x4.shared.b16 {%0,%1,%2,%3}, [%4];" \
        : "=r"(r0), "=r"(r1), "=r"(r2), "=r"(r3) : "r"(addr))

#define LDSM_X4_T(r0,r1,r2,r3,addr) \
    asm volatile("ldmatrix.sync.aligned.m8n8.x4.trans.shared.b16 {%0,%1,%2,%3}, [%4];" \
        : "=r"(r0), "=r"(r1), "=r"(r2), "=r"(r3) : "r"(addr))

#define MMA_F16(c0,c1,c2,c3, a0,a1,a2,a3, b0,b1) \
    asm volatile("mma.sync.aligned.m16n8k16.row.col.f32.f16.f16.f32 " \
        "{%0,%1,%2,%3},{%4,%5,%6,%7},{%8,%9},{%0,%1,%2,%3};" \
        : "+f"(c0), "+f"(c1), "+f"(c2), "+f"(c3) \
        : "r"(a0), "r"(a1), "r"(a2), "r"(a3), "r"(b0), "r"(b1))

#define A_STRIDE 40    // halves per A smem row (32 + 8 pad)  -> 80B
#define B_STRIDE 136   // halves per B smem row (128 + 8 pad) -> 272B

__device__ __forceinline__ unsigned pack_h2(float x, float y) {
    __half2 h = __floats2half2_rn(x, y);
    return *(unsigned*)&h;
}

// OUTMODE: 0 = float out, 1 = float out + relu, 2 = fp16 out (to __half2*)
template<int OUTMODE>
__global__ __launch_bounds__(256)
void gemm_tc_kernel(const float* __restrict__ A,
                    const float* __restrict__ W,
                    const float* __restrict__ bias,
                    float* __restrict__ C,
                    __half2* __restrict__ Ch,
                    int M, int N, int K)
{
    __shared__ __half As[2][128][A_STRIDE];
    __shared__ __half Bs[2][32][B_STRIDE];

    const int bm = blockIdx.y * 128;
    const int bn = blockIdx.x * 128;
    const int tid  = threadIdx.x;
    const int lane = tid & 31;
    const int warp = tid >> 5;
    const int wm = (warp >> 2) * 64;   // 0 / 64
    const int wn = (warp & 3) * 32;    // 0..96

    // loaders: A 128 rows x 32 cols, 2 thr/row x 16 halves
    const int arow  = tid >> 1;
    const int acol  = (tid & 1) * 16;
    // B: 32 rows x 128 cols, 8 thr/row x 16 halves
    const int brow  = tid >> 3;
    const int bcol  = (tid & 7) * 16;

    float c[4][4][4];
    #pragma unroll
    for (int i = 0; i < 4; i++)
        #pragma unroll
        for (int j = 0; j < 4; j++)
            #pragma unroll
            for (int r = 0; r < 4; r++) c[i][j][r] = 0.f;

    const int NT = K >> 5;   // BK = 32
    const bool arow_ok = (bm + arow < M);

    unsigned pa[8], pb[8];   // prefetched halves (16 each)

    const int t0 = 0;
    // ---- prologue: tile 0 ----
    {
        if (arow_ok) {
            const float* ap = A + (size_t)(bm + arow) * K + t0 + acol;
            float4 f0 = *(const float4*)(ap + 0);
            float4 f1 = *(const float4*)(ap + 4);
            float4 f2 = *(const float4*)(ap + 8);
            float4 f3 = *(const float4*)(ap + 12);
            pa[0] = pack_h2(f0.x, f0.y); pa[1] = pack_h2(f0.z, f0.w);
            pa[2] = pack_h2(f1.x, f1.y); pa[3] = pack_h2(f1.z, f1.w);
            pa[4] = pack_h2(f2.x, f2.y); pa[5] = pack_h2(f2.z, f2.w);
            pa[6] = pack_h2(f3.x, f3.y); pa[7] = pack_h2(f3.z, f3.w);
        } else {
            #pragma unroll
            for (int i = 0; i < 8; i++) pa[i] = 0u;
        }
        const float* bp = W + (size_t)brow * N + bn + bcol;
        float4 g0 = *(const float4*)(bp + 0);
        float4 g1 = *(const float4*)(bp + 4);
        float4 g2 = *(const float4*)(bp + 8);
        float4 g3 = *(const float4*)(bp + 12);
        pb[0] = pack_h2(g0.x, g0.y); pb[1] = pack_h2(g0.z, g0.w);
        pb[2] = pack_h2(g1.x, g1.y); pb[3] = pack_h2(g1.z, g1.w);
        pb[4] = pack_h2(g2.x, g2.y); pb[5] = pack_h2(g2.z, g2.w);
        pb[6] = pack_h2(g3.x, g3.y); pb[7] = pack_h2(g3.z, g3.w);

        unsigned* da = (unsigned*)&As[0][arow][acol];
        *(uint4*)(da + 0) = make_uint4(pa[0], pa[1], pa[2], pa[3]);
        *(uint4*)(da + 4) = make_uint4(pa[4], pa[5], pa[6], pa[7]);
        unsigned* db = (unsigned*)&Bs[0][brow][bcol];
        *(uint4*)(db + 0) = make_uint4(pb[0], pb[1], pb[2], pb[3]);
        *(uint4*)(db + 4) = make_uint4(pb[4], pb[5], pb[6], pb[7]);
    }
    __syncthreads();

    for (int t = 0; t < NT; t++) {
        const int cur = t & 1;
        const int nxt = cur ^ 1;

        if (t + 1 < NT) {
            const int k0 = (t + 1) << 5;
            if (arow_ok) {
                const float* ap = A + (size_t)(bm + arow) * K + k0 + acol;
                float4 f0 = *(const float4*)(ap + 0);
                float4 f1 = *(const float4*)(ap + 4);
                float4 f2 = *(const float4*)(ap + 8);
                float4 f3 = *(const float4*)(ap + 12);
                pa[0] = pack_h2(f0.x, f0.y); pa[1] = pack_h2(f0.z, f0.w);
                pa[2] = pack_h2(f1.x, f1.y); pa[3] = pack_h2(f1.z, f1.w);
                pa[4] = pack_h2(f2.x, f2.y); pa[5] = pack_h2(f2.z, f2.w);
                pa[6] = pack_h2(f3.x, f3.y); pa[7] = pack_h2(f3.z, f3.w);
            } else {
                #pragma unroll
                for (int i = 0; i < 8; i++) pa[i] = 0u;
            }
            const float* bp = W + (size_t)(k0 + brow) * N + bn + bcol;
            float4 g0 = *(const float4*)(bp + 0);
            float4 g1 = *(const float4*)(bp + 4);
            float4 g2 = *(const float4*)(bp + 8);
            float4 g3 = *(const float4*)(bp + 12);
            pb[0] = pack_h2(g0.x, g0.y); pb[1] = pack_h2(g0.z, g0.w);
            pb[2] = pack_h2(g1.x, g1.y); pb[3] = pack_h2(g1.z, g1.w);
            pb[4] = pack_h2(g2.x, g2.y); pb[5] = pack_h2(g2.z, g2.w);
            pb[6] = pack_h2(g3.x, g3.y); pb[7] = pack_h2(g3.z, g3.w);
        }

        #pragma unroll
        for (int kk = 0; kk < 32; kk += 16) {
            unsigned af[4][4], bf[4][2];
            #pragma unroll
            for (int mt = 0; mt < 4; mt++) {
                unsigned addr = (unsigned)__cvta_generic_to_shared(
                    &As[cur][wm + mt * 16 + (lane & 15)][kk + ((lane >> 4) << 3)]);
                LDSM_X4(af[mt][0], af[mt][1], af[mt][2], af[mt][3], addr);
            }
            #pragma unroll
            for (int ntp = 0; ntp < 2; ntp++) {
                unsigned addr = (unsigned)__cvta_generic_to_shared(
                    &Bs[cur][kk + (lane & 15)][wn + ntp * 16 + ((lane >> 4) << 3)]);
                unsigned r0, r1, r2, r3;
                LDSM_X4_T(r0, r1, r2, r3, addr);
                bf[2 * ntp][0] = r0; bf[2 * ntp][1] = r1;
                bf[2 * ntp + 1][0] = r2; bf[2 * ntp + 1][1] = r3;
            }
            #pragma unroll
            for (int mt = 0; mt < 4; mt++)
                #pragma unroll
                for (int nt = 0; nt < 4; nt++)
                    MMA_F16(c[mt][nt][0], c[mt][nt][1], c[mt][nt][2], c[mt][nt][3],
                            af[mt][0], af[mt][1], af[mt][2], af[mt][3],
                            bf[nt][0], bf[nt][1]);
        }

        if (t + 1 < NT) {
            unsigned* da = (unsigned*)&As[nxt][arow][acol];
            *(uint4*)(da + 0) = make_uint4(pa[0], pa[1], pa[2], pa[3]);
            *(uint4*)(da + 4) = make_uint4(pa[4], pa[5], pa[6], pa[7]);
            unsigned* db = (unsigned*)&Bs[nxt][brow][bcol];
            *(uint4*)(db + 0) = make_uint4(pb[0], pb[1], pb[2], pb[3]);
            *(uint4*)(db + 4) = make_uint4(pb[4], pb[5], pb[6], pb[7]);
        }
        __syncthreads();
    }

    const int grow = lane >> 2;
    #pragma unroll
    for (int mt = 0; mt < 4; mt++) {
        int row0 = bm + wm + mt * 16 + grow;
        #pragma unroll
        for (int nt = 0; nt < 4; nt++) {
            int gn = bn + wn + nt * 8 + (lane & 3) * 2;
            float b0 = bias[gn], b1 = bias[gn + 1];
            float v0 = c[mt][nt][0] + b0;
            float v1 = c[mt][nt][1] + b1;
            float v2 = c[mt][nt][2] + b0;
            float v3 = c[mt][nt][3] + b1;
            if (OUTMODE == 1) {
                v0 = fmaxf(v0, 0.f); v1 = fmaxf(v1, 0.f);
                v2 = fmaxf(v2, 0.f); v3 = fmaxf(v3, 0.f);
            }
            if (OUTMODE == 2) {
                if (row0 < M)
                    Ch[((size_t)row0 * N + gn) >> 1] = __floats2half2_rn(v0, v1);
                if (row0 + 8 < M)
                    Ch[((size_t)(row0 + 8) * N + gn) >> 1] = __floats2half2_rn(v2, v3);
            } else {
                if (row0 < M)
                    *(float2*)(C + (size_t)row0 * N + gn) = make_float2(v0, v1);
                if (row0 + 8 < M)
                    *(float2*)(C + (size_t)(row0 + 8) * N + gn) = make_float2(v2, v3);
            }
        }
    }
}

// ---------------- MSDA: fp16 value, 2 heads per warp -------------------------
__global__ __launch_bounds__(256)
void msda_h_kernel(const __half2* __restrict__ value,
                   const float* __restrict__ off,
                   const float* __restrict__ attn_logits,
                   const float* __restrict__ ref,
                   float* __restrict__ out)
{
    constexpr int kH[4]  = {100, 50, 25, 13};
    constexpr int kW[4]  = {100, 50, 25, 13};
    constexpr int kSt[4] = {0, 10000, 12500, 13125};

    int gwarp = (blockIdx.x * blockDim.x + threadIdx.x) >> 5;
    int lane  = threadIdx.x & 31;
    const int NUNITS = B_SZ * S_TOTAL * 4;     // (bq, head-pair)
    if (gwarp >= NUNITS) return;

    int hp = gwarp & 3;
    int bq = gwarp >> 2;
    int b  = (bq >= S_TOTAL) ? 1 : 0;
    int hh  = lane >> 4;
    int ch2 = lane & 15;
    int h   = hp * 2 + hh;

    float2 offv = __ldg((const float2*)(off + (size_t)bq * 256 + h * 32) + ch2);

    float v = __ldg(attn_logits + (size_t)bq * 128 + h * 16 + ch2);
    float m = v;
    #pragma unroll
    for (int o = 8; o > 0; o >>= 1) m = fmaxf(m, __shfl_xor_sync(0xffffffffu, m, o));
    float e = __expf(v - m);
    float ssum = e;
    #pragma unroll
    for (int o = 8; o > 0; o >>= 1) ssum += __shfl_xor_sync(0xffffffffu, ssum, o);
    float aw = e / ssum;

    const float* refp = ref + (size_t)bq * (NL * 2);

    float accx = 0.f, accy = 0.f;
    #pragma unroll
    for (int l = 0; l < NL; l++) {
        const int H_ = kH[l], W_ = kW[l];
        const float fW = (float)W_, fH = (float)H_;
        const float invW = 1.f / fW, invH = 1.f / fH;
        float refx = __ldg(refp + l * 2 + 0);
        float refy = __ldg(refp + l * 2 + 1);
        const __half2* vbase = value + ((size_t)(b * S_TOTAL + kSt[l]) * NH + h) * 16 + ch2;

        #pragma unroll
        for (int p = 0; p < NP; p++) {
            const int idx16 = l * NP + p;
            const int src = hh * 16 + idx16;
            float w16 = __shfl_sync(0xffffffffu, aw, src);
            float ox  = __shfl_sync(0xffffffffu, offv.x, src);
            float oy  = __shfl_sync(0xffffffffu, offv.y, src);

            float x = (refx + ox * invW) * fW - 0.5f;
            float y = (refy + oy * invH) * fH - 0.5f;
            float x0f = floorf(x), y0f = floorf(y);
            int x0 = (int)x0f, y0 = (int)y0f;
            float fx = x - x0f, fy = y - y0f;

            float mx0 = ((unsigned)x0     < (unsigned)W_) ? 1.f : 0.f;
            float mx1 = ((unsigned)(x0+1) < (unsigned)W_) ? 1.f : 0.f;
            float my0 = ((unsigned)y0     < (unsigned)H_) ? 1.f : 0.f;
            float my1 = ((unsigned)(y0+1) < (unsigned)H_) ? 1.f : 0.f;

            float gx1 = fx * mx1, gx0 = (1.f - fx) * mx0;
            float gy1 = fy * my1, gy0 = (1.f - fy) * my0;
            float w00 = gx0 * gy0, w10 = gx1 * gy0;
            float w01 = gx0 * gy1, w11 = gx1 * gy1;

            int cx0 = min(max(x0, 0), W_ - 1);
            int cx1 = min(max(x0 + 1, 0), W_ - 1);
            int cy0 = min(max(y0, 0), H_ - 1);
            int cy1 = min(max(y0 + 1, 0), H_ - 1);
            int r0 = cy0 * W_, r1 = cy1 * W_;

            __half2 h00 = __ldg(vbase + (size_t)(r0 + cx0) * 128);
            __half2 h10 = __ldg(vbase + (size_t)(r0 + cx1) * 128);
            __half2 h01 = __ldg(vbase + (size_t)(r1 + cx0) * 128);
            __half2 h11 = __ldg(vbase + (size_t)(r1 + cx1) * 128);

            float2 f00 = __half22float2(h00);
            float2 f10 = __half22float2(h10);
            float2 f01 = __half22float2(h01);
            float2 f11 = __half22float2(h11);

            float sx = fmaf(w00, f00.x, fmaf(w10, f10.x, fmaf(w01, f01.x, w11 * f11.x)));
            float sy = fmaf(w00, f00.y, fmaf(w10, f10.y, fmaf(w01, f01.y, w11 * f11.y)));
            accx = fmaf(w16, sx, accx);
            accy = fmaf(w16, sy, accy);
        }
    }
    *(float2*)(out + ((size_t)bq * NH + h) * DH + 2 * ch2) = make_float2(accx, accy);
}

// ---------------- residual add + LayerNorm (one block per row, 256 thr) -----
__global__ void add_ln_kernel(const float* __restrict__ xin,
                              const float* __restrict__ r,
                              const float* __restrict__ g,
                              const float* __restrict__ bt,
                              float* __restrict__ xout)
{
    int row = blockIdx.x;
    int t = threadIdx.x;
    float v = xin[(size_t)row * 256 + t] + r[(size_t)row * 256 + t];

    float s1 = v, s2 = v * v;
    #pragma unroll
    for (int o = 16; o > 0; o >>= 1) {
        s1 += __shfl_xor_sync(0xffffffffu, s1, o);
        s2 += __shfl_xor_sync(0xffffffffu, s2, o);
    }
    __shared__ float sh1[8], sh2[8];
    int w = t >> 5, lane = t & 31;
    if (lane == 0) { sh1[w] = s1; sh2[w] = s2; }
    __syncthreads();
    if (w == 0) {
        s1 = (lane < 8) ? sh1[lane] : 0.f;
        s2 = (lane < 8) ? sh2[lane] : 0.f;
        #pragma unroll
        for (int o = 4; o > 0; o >>= 1) {
            s1 += __shfl_xor_sync(0xffffffffu, s1, o);
            s2 += __shfl_xor_sync(0xffffffffu, s2, o);
        }
        if (lane == 0) { sh1[0] = s1; sh2[0] = s2; }
    }
    __syncthreads();
    float mean = sh1[0] * (1.f / 256.f);
    float var  = sh2[0] * (1.f / 256.f) - mean * mean;
    float inv  = rsqrtf(var + 1e-5f);
    xout[(size_t)row * 256 + t] = (v - mean) * inv * g[t] + bt[t];
}

// -----------------------------------------------------------------------------
extern "C" void kernel_launch(void* const* d_in, const int* in_sizes, int n_in,
                              void* d_out, int out_size)
{
    const float* src    = (const float*)d_in[0];
    const float* vr     = (const float*)d_in[2];
    const float* W_off  = (const float*)d_in[3];
    const float* b_off  = (const float*)d_in[4];
    const float* W_attn = (const float*)d_in[5];
    const float* b_attn = (const float*)d_in[6];
    const float* W_val  = (const float*)d_in[7];
    const float* b_val  = (const float*)d_in[8];
    const float* W_out  = (const float*)d_in[9];
    const float* b_out  = (const float*)d_in[10];
    const float* ln1_g  = (const float*)d_in[11];
    const float* ln1_b  = (const float*)d_in[12];
    const float* W1     = (const float*)d_in[13];
    const float* b1     = (const float*)d_in[14];
    const float* W2     = (const float*)d_in[15];
    const float* b2     = (const float*)d_in[16];
    const float* ln2_g  = (const float*)d_in[17];
    const float* ln2_b  = (const float*)d_in[18];

    __half2* valueh;
    float *off, *attn, *msda, *tmp, *xb, *hid, *refp;
    cudaGetSymbolAddress((void**)&valueh, g_value_h);
    cudaGetSymbolAddress((void**)&off,   g_off);
    cudaGetSymbolAddress((void**)&attn,  g_attn);
    cudaGetSymbolAddress((void**)&msda,  g_msda);
    cudaGetSymbolAddress((void**)&tmp,   g_tmp);
    cudaGetSymbolAddress((void**)&xb,    g_x);
    cudaGetSymbolAddress((void**)&hid,   g_hid);
    cudaGetSymbolAddress((void**)&refp,  g_ref);

    const int M = M_TOTAL;
    const int GM = (M + 127) / 128;   // 208

    ref_kernel<<<(M + 255) / 256, 256>>>(vr, refp);

    for (int i = 0; i < NUM_LAYERS; i++) {
        const float* xin = (i == 0) ? src : xb;

        gemm_tc_kernel<2><<<dim3(2, GM), 256>>>(xin, W_val + (size_t)i * 256 * 256,
                                                b_val + i * 256, nullptr, valueh, M, 256, 256);
        gemm_tc_kernel<0><<<dim3(2, GM), 256>>>(xin, W_off + (size_t)i * 256 * 256,
                                                b_off + i * 256, off, nullptr, M, 256, 256);
        gemm_tc_kernel<0><<<dim3(1, GM), 256>>>(xin, W_attn + (size_t)i * 256 * 128,
                                                b_attn + i * 128, attn, nullptr, M, 128, 256);

        int nunits = B_SZ * S_TOTAL * 4;
        msda_h_kernel<<<(nunits * 32 + 255) / 256, 256>>>(valueh, off, attn, refp, msda);

        gemm_tc_kernel<0><<<dim3(2, GM), 256>>>(msda, W_out + (size_t)i * 256 * 256,
                                                b_out + i * 256, tmp, nullptr, M, 256, 256);
        add_ln_kernel<<<M, 256>>>(xin, tmp, ln1_g + i * 256, ln1_b + i * 256, xb);

        gemm_tc_kernel<1><<<dim3(8, GM), 256>>>(xb, W1 + (size_t)i * 256 * 1024,
                                                b1 + i * 1024, hid, nullptr, M, 1024, 256);
        gemm_tc_kernel<0><<<dim3(2, GM), 256>>>(hid, W2 + (size_t)i * 1024 * 256,
                                                b2 + i * 256, tmp, nullptr, M, 256, 1024);

        float* lnout = (i == NUM_LAYERS - 1) ? (float*)d_out : xb;
        add_ln_kernel<<<M, 256>>>(xb, tmp, ln2_g + i * 256, ln2_b + i * 256, lnout);
    }
}

// round 10
// speedup vs baseline: 2.3302x; 1.2734x over previous
#include <cuda_runtime.h>
#include <cuda_fp16.h>
#include <cuda_bf16.h>
#include <math.h>

#define NUM_LAYERS 2
#define B_SZ 2
#define S_TOTAL 13294
#define D_MODEL 256
#define NH 8
#define DH 32
#define NL 4
#define NP 4
#define DFF 1024
#define M_TOTAL (B_SZ * S_TOTAL)
#define PAD_M 26624            /* 208 * 128 */

__constant__ int c_H[4]     = {100, 50, 25, 13};
__constant__ int c_W[4]     = {100, 50, 25, 13};
__constant__ int c_start[4] = {0, 10000, 12500, 13125};

// ---------------- scratch (static device globals; no allocation) -------------
__device__ __align__(16) __half2 g_value_h[PAD_M * 128];  // value fp16 [row][128 half2]
__device__ __align__(16) __half  g_x16   [PAD_M * 256];   // fp16 copy of x (GEMM A)
__device__ __align__(16) __half2 g_msda16[PAD_M * 128];   // MSDA out fp16
__device__ __align__(16) __half  g_hid16 [PAD_M * DFF];   // FFN hidden fp16
__device__ float g_off  [M_TOTAL * D_MODEL];
__device__ float g_attn [M_TOTAL * 128];
__device__ float g_tmp  [M_TOTAL * D_MODEL];
__device__ float g_x    [M_TOTAL * D_MODEL];
__device__ float g_ref  [M_TOTAL * NL * 2];
// fp16 weights
__device__ __align__(16) __half g_wval16 [NUM_LAYERS * 256 * 256];
__device__ __align__(16) __half g_woff16 [NUM_LAYERS * 256 * 256];
__device__ __align__(16) __half g_wattn16[NUM_LAYERS * 256 * 128];
__device__ __align__(16) __half g_wout16 [NUM_LAYERS * 256 * 256];
__device__ __align__(16) __half g_w1_16  [NUM_LAYERS * 256 * 1024];
__device__ __align__(16) __half g_w2_16  [NUM_LAYERS * 1024 * 256];

// ---------------- fp32 -> fp16 conversion ------------------------------------
__global__ void cvt_kernel(const float* __restrict__ in, __half* __restrict__ out, int n)
{
    int i = (blockIdx.x * blockDim.x + threadIdx.x) * 2;
    if (i < n) {
        float2 f = *(const float2*)(in + i);
        *(__half2*)(out + i) = __floats2half2_rn(f.x, f.y);
    }
}

// ---------------- reference points ------------------------------------------
__global__ void ref_kernel(const float* __restrict__ vr, float* __restrict__ ref)
{
    int idx = blockIdx.x * blockDim.x + threadIdx.x;
    if (idx >= B_SZ * S_TOTAL) return;
    int b = idx / S_TOTAL;
    int s = idx % S_TOTAL;

    int lvl = 0, rem = s;
    while (lvl < 3 && rem >= c_H[lvl] * c_W[lvl]) { rem -= c_H[lvl] * c_W[lvl]; lvl++; }
    int W_ = c_W[lvl], H_ = c_H[lvl];
    int i = rem / W_, j = rem % W_;

    float vrx = vr[(b * NL + lvl) * 2 + 0];
    float vry = vr[(b * NL + lvl) * 2 + 1];
    float bx = (j + 0.5f) / (vrx * (float)W_);
    float by = (i + 0.5f) / (vry * (float)H_);

    #pragma unroll
    for (int l = 0; l < NL; l++) {
        float vx = vr[(b * NL + l) * 2 + 0];
        float vy = vr[(b * NL + l) * 2 + 1];
        ref[((size_t)idx * NL + l) * 2 + 0] = bx * vx;
        ref[((size_t)idx * NL + l) * 2 + 1] = by * vy;
    }
}

// ---------------- FP16 GEMM: cp.async 4-stage + ldmatrix + m16n8k16 ----------
// C[M,N] = A[M,K] @ W[K,N] + bias ; A,W fp16, accum fp32.
// BM=BN=128, BK=32, 256 threads = 8 warps (2Mx4N), warp tile 64x32.

#define LDSM_X4(r0,r1,r2,r3,addr) \
    asm volatile("ldmatrix.sync.aligned.m8n8.x4.shared.b16 {%0,%1,%2,%3}, [%4];" \
        : "=r"(r0), "=r"(r1), "=r"(r2), "=r"(r3) : "r"(addr))

#define LDSM_X4_T(r0,r1,r2,r3,addr) \
    asm volatile("ldmatrix.sync.aligned.m8n8.x4.trans.shared.b16 {%0,%1,%2,%3}, [%4];" \
        : "=r"(r0), "=r"(r1), "=r"(r2), "=r"(r3) : "r"(addr))

#define MMA_F16(c0,c1,c2,c3, a0,a1,a2,a3, b0,b1) \
    asm volatile("mma.sync.aligned.m16n8k16.row.col.f32.f16.f16.f32 " \
        "{%0,%1,%2,%3},{%4,%5,%6,%7},{%8,%9},{%0,%1,%2,%3};" \
        : "+f"(c0), "+f"(c1), "+f"(c2), "+f"(c3) \
        : "r"(a0), "r"(a1), "r"(a2), "r"(a3), "r"(b0), "r"(b1))

#define CP_ASYNC16(smem_addr, gptr) \
    asm volatile("cp.async.cg.shared.global [%0], [%1], 16;" \
        :: "r"(smem_addr), "l"(gptr))

#define CP_COMMIT() asm volatile("cp.async.commit_group;")
#define CP_WAIT(n)  asm volatile("cp.async.wait_group %0;" :: "n"(n))

#define A_STRIDE 40    // halves per A smem row (80B, 16B-multiple)
#define B_STRIDE 136   // halves per B smem row (272B, 16B-multiple)
#define STAGES 4
#define SMEM_BYTES (STAGES * (128 * A_STRIDE + 32 * B_STRIDE) * 2)

// OUTMODE: 0 = float out, 1 = fp16 out + relu, 2 = fp16 out
template<int OUTMODE>
__global__ __launch_bounds__(256)
void gemm_tc_kernel(const __half* __restrict__ A,
                    const __half* __restrict__ W,
                    const float* __restrict__ bias,
                    float* __restrict__ C,
                    __half2* __restrict__ Ch,
                    int M, int N, int K)
{
    extern __shared__ __align__(16) __half smem[];
    __half* AsBase = smem;                               // [STAGES][128][A_STRIDE]
    __half* BsBase = smem + STAGES * 128 * A_STRIDE;     // [STAGES][32][B_STRIDE]

    const int bm = blockIdx.y * 128;
    const int bn = blockIdx.x * 128;
    const int tid  = threadIdx.x;
    const int lane = tid & 31;
    const int warp = tid >> 5;
    const int wm = (warp >> 2) * 64;   // 0 / 64
    const int wn = (warp & 3) * 32;    // 0..96

    // cp.async loader mapping
    const int arow = tid >> 1;              // 0..127
    const int aseg = (tid & 1) * 2;         // segments {0,1} or {2,3}; each 8 halves
    const int brow = tid >> 3;              // 0..31
    const int bseg = (tid & 7) * 2;         // segments 0..15, two each

    float c[4][4][4];
    #pragma unroll
    for (int i = 0; i < 4; i++)
        #pragma unroll
        for (int j = 0; j < 4; j++)
            #pragma unroll
            for (int r = 0; r < 4; r++) c[i][j][r] = 0.f;

    const int NT = K >> 5;   // BK = 32

    auto load_tile = [&](int stage, int k0) {
        // A: 128 rows x 64B (2 x 16B per thread)
        const __half* ga = A + (size_t)(bm + arow) * K + k0 + aseg * 8;
        unsigned da = (unsigned)__cvta_generic_to_shared(
            AsBase + (stage * 128 + arow) * A_STRIDE + aseg * 8);
        CP_ASYNC16(da, ga);
        CP_ASYNC16(da + 16, ga + 8);
        // B: 32 rows x 256B (2 x 16B per thread)
        const __half* gb = W + (size_t)(k0 + brow) * N + bn + bseg * 8;
        unsigned db = (unsigned)__cvta_generic_to_shared(
            BsBase + (stage * 32 + brow) * B_STRIDE + bseg * 8);
        CP_ASYNC16(db, gb);
        CP_ASYNC16(db + 16, gb + 8);
    };

    // prologue: stage 0..STAGES-2
    #pragma unroll
    for (int s = 0; s < STAGES - 1; s++) {
        if (s < NT) load_tile(s, s << 5);
        CP_COMMIT();
    }
    CP_WAIT(STAGES - 2);
    __syncthreads();

    for (int t = 0; t < NT; t++) {
        const int cur = t % STAGES;
        const __half* Acur = AsBase + cur * 128 * A_STRIDE;
        const __half* Bcur = BsBase + cur * 32 * B_STRIDE;

        #pragma unroll
        for (int kk = 0; kk < 32; kk += 16) {
            unsigned af[4][4], bf[4][2];
            #pragma unroll
            for (int mt = 0; mt < 4; mt++) {
                unsigned addr = (unsigned)__cvta_generic_to_shared(
                    Acur + (wm + mt * 16 + (lane & 15)) * A_STRIDE + kk + ((lane >> 4) << 3));
                LDSM_X4(af[mt][0], af[mt][1], af[mt][2], af[mt][3], addr);
            }
            #pragma unroll
            for (int ntp = 0; ntp < 2; ntp++) {
                unsigned addr = (unsigned)__cvta_generic_to_shared(
                    Bcur + (kk + (lane & 15)) * B_STRIDE + wn + ntp * 16 + ((lane >> 4) << 3));
                unsigned r0, r1, r2, r3;
                LDSM_X4_T(r0, r1, r2, r3, addr);
                bf[2 * ntp][0] = r0; bf[2 * ntp][1] = r1;
                bf[2 * ntp + 1][0] = r2; bf[2 * ntp + 1][1] = r3;
            }
            #pragma unroll
            for (int mt = 0; mt < 4; mt++)
                #pragma unroll
                for (int nt = 0; nt < 4; nt++)
                    MMA_F16(c[mt][nt][0], c[mt][nt][1], c[mt][nt][2], c[mt][nt][3],
                            af[mt][0], af[mt][1], af[mt][2], af[mt][3],
                            bf[nt][0], bf[nt][1]);
        }

        // issue loads for stage t+STAGES-1 (into slot consumed at t-1)
        int tn = t + STAGES - 1;
        if (tn < NT) load_tile(tn % STAGES, tn << 5);
        CP_COMMIT();
        CP_WAIT(STAGES - 2);
        __syncthreads();
    }

    const int grow = lane >> 2;
    #pragma unroll
    for (int mt = 0; mt < 4; mt++) {
        int row0 = bm + wm + mt * 16 + grow;
        #pragma unroll
        for (int nt = 0; nt < 4; nt++) {
            int gn = bn + wn + nt * 8 + (lane & 3) * 2;
            float b0 = bias[gn], b1 = bias[gn + 1];
            float v0 = c[mt][nt][0] + b0;
            float v1 = c[mt][nt][1] + b1;
            float v2 = c[mt][nt][2] + b0;
            float v3 = c[mt][nt][3] + b1;
            if (OUTMODE == 1) {
                v0 = fmaxf(v0, 0.f); v1 = fmaxf(v1, 0.f);
                v2 = fmaxf(v2, 0.f); v3 = fmaxf(v3, 0.f);
            }
            if (OUTMODE >= 1) {
                if (row0 < M)
                    Ch[((size_t)row0 * N + gn) >> 1] = __floats2half2_rn(v0, v1);
                if (row0 + 8 < M)
                    Ch[((size_t)(row0 + 8) * N + gn) >> 1] = __floats2half2_rn(v2, v3);
            } else {
                if (row0 < M)
                    *(float2*)(C + (size_t)row0 * N + gn) = make_float2(v0, v1);
                if (row0 + 8 < M)
                    *(float2*)(C + (size_t)(row0 + 8) * N + gn) = make_float2(v2, v3);
            }
        }
    }
}

// ---------------- MSDA: fp16 value, 2 heads per warp, fp16 out ---------------
__global__ __launch_bounds__(256)
void msda_h_kernel(const __half2* __restrict__ value,
                   const float* __restrict__ off,
                   const float* __restrict__ attn_logits,
                   const float* __restrict__ ref,
                   __half2* __restrict__ out)
{
    constexpr int kH[4]  = {100, 50, 25, 13};
    constexpr int kW[4]  = {100, 50, 25, 13};
    constexpr int kSt[4] = {0, 10000, 12500, 13125};

    int gwarp = (blockIdx.x * blockDim.x + threadIdx.x) >> 5;
    int lane  = threadIdx.x & 31;
    const int NUNITS = B_SZ * S_TOTAL * 4;     // (bq, head-pair)
    if (gwarp >= NUNITS) return;

    int hp = gwarp & 3;
    int bq = gwarp >> 2;
    int b  = (bq >= S_TOTAL) ? 1 : 0;
    int hh  = lane >> 4;
    int ch2 = lane & 15;
    int h   = hp * 2 + hh;

    float2 offv = __ldg((const float2*)(off + (size_t)bq * 256 + h * 32) + ch2);

    float v = __ldg(attn_logits + (size_t)bq * 128 + h * 16 + ch2);
    float m = v;
    #pragma unroll
    for (int o = 8; o > 0; o >>= 1) m = fmaxf(m, __shfl_xor_sync(0xffffffffu, m, o));
    float e = __expf(v - m);
    float ssum = e;
    #pragma unroll
    for (int o = 8; o > 0; o >>= 1) ssum += __shfl_xor_sync(0xffffffffu, ssum, o);
    float aw = e / ssum;

    const float* refp = ref + (size_t)bq * (NL * 2);

    float accx = 0.f, accy = 0.f;
    #pragma unroll
    for (int l = 0; l < NL; l++) {
        const int H_ = kH[l], W_ = kW[l];
        const float fW = (float)W_, fH = (float)H_;
        const float invW = 1.f / fW, invH = 1.f / fH;
        float refx = __ldg(refp + l * 2 + 0);
        float refy = __ldg(refp + l * 2 + 1);
        const __half2* vbase = value + ((size_t)(b * S_TOTAL + kSt[l]) * NH + h) * 16 + ch2;

        #pragma unroll
        for (int p = 0; p < NP; p++) {
            const int idx16 = l * NP + p;
            const int src = hh * 16 + idx16;
            float w16 = __shfl_sync(0xffffffffu, aw, src);
            float ox  = __shfl_sync(0xffffffffu, offv.x, src);
            float oy  = __shfl_sync(0xffffffffu, offv.y, src);

            float x = (refx + ox * invW) * fW - 0.5f;
            float y = (refy + oy * invH) * fH - 0.5f;
            float x0f = floorf(x), y0f = floorf(y);
            int x0 = (int)x0f, y0 = (int)y0f;
            float fx = x - x0f, fy = y - y0f;

            float mx0 = ((unsigned)x0     < (unsigned)W_) ? 1.f : 0.f;
            float mx1 = ((unsigned)(x0+1) < (unsigned)W_) ? 1.f : 0.f;
            float my0 = ((unsigned)y0     < (unsigned)H_) ? 1.f : 0.f;
            float my1 = ((unsigned)(y0+1) < (unsigned)H_) ? 1.f : 0.f;

            float gx1 = fx * mx1, gx0 = (1.f - fx) * mx0;
            float gy1 = fy * my1, gy0 = (1.f - fy) * my0;
            float w00 = gx0 * gy0, w10 = gx1 * gy0;
            float w01 = gx0 * gy1, w11 = gx1 * gy1;

            int cx0 = min(max(x0, 0), W_ - 1);
            int cx1 = min(max(x0 + 1, 0), W_ - 1);
            int cy0 = min(max(y0, 0), H_ - 1);
            int cy1 = min(max(y0 + 1, 0), H_ - 1);
            int r0 = cy0 * W_, r1 = cy1 * W_;

            __half2 h00 = __ldg(vbase + (size_t)(r0 + cx0) * 128);
            __half2 h10 = __ldg(vbase + (size_t)(r0 + cx1) * 128);
            __half2 h01 = __ldg(vbase + (size_t)(r1 + cx0) * 128);
            __half2 h11 = __ldg(vbase + (size_t)(r1 + cx1) * 128);

            float2 f00 = __half22float2(h00);
            float2 f10 = __half22float2(h10);
            float2 f01 = __half22float2(h01);
            float2 f11 = __half22float2(h11);

            float sx = fmaf(w00, f00.x, fmaf(w10, f10.x, fmaf(w01, f01.x, w11 * f11.x)));
            float sy = fmaf(w00, f00.y, fmaf(w10, f10.y, fmaf(w01, f01.y, w11 * f11.y)));
            accx = fmaf(w16, sx, accx);
            accy = fmaf(w16, sy, accy);
        }
    }
    out[(size_t)bq * 128 + h * 16 + ch2] = __floats2half2_rn(accx, accy);
}

// -------- residual add + LayerNorm; writes fp32 + fp16 copy ------------------
__global__ void add_ln_kernel(const float* __restrict__ xin,
                              const float* __restrict__ r,
                              const float* __restrict__ g,
                              const float* __restrict__ bt,
                              float* __restrict__ xout,
                              __half* __restrict__ xout16)
{
    int row = blockIdx.x;
    int t = threadIdx.x;
    float v = xin[(size_t)row * 256 + t] + r[(size_t)row * 256 + t];

    float s1 = v, s2 = v * v;
    #pragma unroll
    for (int o = 16; o > 0; o >>= 1) {
        s1 += __shfl_xor_sync(0xffffffffu, s1, o);
        s2 += __shfl_xor_sync(0xffffffffu, s2, o);
    }
    __shared__ float sh1[8], sh2[8];
    int w = t >> 5, lane = t & 31;
    if (lane == 0) { sh1[w] = s1; sh2[w] = s2; }
    __syncthreads();
    if (w == 0) {
        s1 = (lane < 8) ? sh1[lane] : 0.f;
        s2 = (lane < 8) ? sh2[lane] : 0.f;
        #pragma unroll
        for (int o = 4; o > 0; o >>= 1) {
            s1 += __shfl_xor_sync(0xffffffffu, s1, o);
            s2 += __shfl_xor_sync(0xffffffffu, s2, o);
        }
        if (lane == 0) { sh1[0] = s1; sh2[0] = s2; }
    }
    __syncthreads();
    float mean = sh1[0] * (1.f / 256.f);
    float var  = sh2[0] * (1.f / 256.f) - mean * mean;
    float inv  = rsqrtf(var + 1e-5f);
    float o = (v - mean) * inv * g[t] + bt[t];
    xout[(size_t)row * 256 + t] = o;
    xout16[(size_t)row * 256 + t] = __float2half(o);
}

// -----------------------------------------------------------------------------
extern "C" void kernel_launch(void* const* d_in, const int* in_sizes, int n_in,
                              void* d_out, int out_size)
{
    const float* src    = (const float*)d_in[0];
    const float* vr     = (const float*)d_in[2];
    const float* W_off  = (const float*)d_in[3];
    const float* b_off  = (const float*)d_in[4];
    const float* W_attn = (const float*)d_in[5];
    const float* b_attn = (const float*)d_in[6];
    const float* W_val  = (const float*)d_in[7];
    const float* b_val  = (const float*)d_in[8];
    const float* W_out  = (const float*)d_in[9];
    const float* b_out  = (const float*)d_in[10];
    const float* ln1_g  = (const float*)d_in[11];
    const float* ln1_b  = (const float*)d_in[12];
    const float* W1     = (const float*)d_in[13];
    const float* b1     = (const float*)d_in[14];
    const float* W2     = (const float*)d_in[15];
    const float* b2     = (const float*)d_in[16];
    const float* ln2_g  = (const float*)d_in[17];
    const float* ln2_b  = (const float*)d_in[18];

    __half2 *valueh, *msda16;
    __half *x16, *hid16, *wval16, *woff16, *wattn16, *wout16, *w1_16, *w2_16;
    float *off, *attn, *tmp, *xb, *refp;
    cudaGetSymbolAddress((void**)&valueh,  g_value_h);
    cudaGetSymbolAddress((void**)&msda16,  g_msda16);
    cudaGetSymbolAddress((void**)&x16,     g_x16);
    cudaGetSymbolAddress((void**)&hid16,   g_hid16);
    cudaGetSymbolAddress((void**)&wval16,  g_wval16);
    cudaGetSymbolAddress((void**)&woff16,  g_woff16);
    cudaGetSymbolAddress((void**)&wattn16, g_wattn16);
    cudaGetSymbolAddress((void**)&wout16,  g_wout16);
    cudaGetSymbolAddress((void**)&w1_16,   g_w1_16);
    cudaGetSymbolAddress((void**)&w2_16,   g_w2_16);
    cudaGetSymbolAddress((void**)&off,   g_off);
    cudaGetSymbolAddress((void**)&attn,  g_attn);
    cudaGetSymbolAddress((void**)&tmp,   g_tmp);
    cudaGetSymbolAddress((void**)&xb,    g_x);
    cudaGetSymbolAddress((void**)&refp,  g_ref);

    cudaFuncSetAttribute(gemm_tc_kernel<0>, cudaFuncAttributeMaxDynamicSharedMemorySize, SMEM_BYTES);
    cudaFuncSetAttribute(gemm_tc_kernel<1>, cudaFuncAttributeMaxDynamicSharedMemorySize, SMEM_BYTES);
    cudaFuncSetAttribute(gemm_tc_kernel<2>, cudaFuncAttributeMaxDynamicSharedMemorySize, SMEM_BYTES);

    const int M = M_TOTAL;
    const int GM = (M + 127) / 128;   // 208

    // one-time conversions (inside graph; cheap)
    auto cvt = [&](const float* in, __half* out, int n) {
        cvt_kernel<<<(n / 2 + 255) / 256, 256>>>(in, out, n);
    };
    cvt(W_val,  wval16,  NUM_LAYERS * 256 * 256);
    cvt(W_off,  woff16,  NUM_LAYERS * 256 * 256);
    cvt(W_attn, wattn16, NUM_LAYERS * 256 * 128);
    cvt(W_out,  wout16,  NUM_LAYERS * 256 * 256);
    cvt(W1,     w1_16,   NUM_LAYERS * 256 * 1024);
    cvt(W2,     w2_16,   NUM_LAYERS * 1024 * 256);
    cvt(src,    x16,     M * 256);

    ref_kernel<<<(M + 255) / 256, 256>>>(vr, refp);

    for (int i = 0; i < NUM_LAYERS; i++) {
        const float* xin = (i == 0) ? src : xb;   // fp32 residual source

        gemm_tc_kernel<2><<<dim3(2, GM), 256, SMEM_BYTES>>>(
            x16, wval16 + (size_t)i * 256 * 256, b_val + i * 256,
            nullptr, valueh, M, 256, 256);
        gemm_tc_kernel<0><<<dim3(2, GM), 256, SMEM_BYTES>>>(
            x16, woff16 + (size_t)i * 256 * 256, b_off + i * 256,
            off, nullptr, M, 256, 256);
        gemm_tc_kernel<0><<<dim3(1, GM), 256, SMEM_BYTES>>>(
            x16, wattn16 + (size_t)i * 256 * 128, b_attn + i * 128,
            attn, nullptr, M, 128, 256);

        int nunits = B_SZ * S_TOTAL * 4;
        msda_h_kernel<<<(nunits * 32 + 255) / 256, 256>>>(valueh, off, attn, refp, msda16);

        gemm_tc_kernel<0><<<dim3(2, GM), 256, SMEM_BYTES>>>(
            (const __half*)msda16, wout16 + (size_t)i * 256 * 256, b_out + i * 256,
            tmp, nullptr, M, 256, 256);
        add_ln_kernel<<<M, 256>>>(xin, tmp, ln1_g + i * 256, ln1_b + i * 256, xb, x16);

        gemm_tc_kernel<1><<<dim3(8, GM), 256, SMEM_BYTES>>>(
            x16, w1_16 + (size_t)i * 256 * 1024, b1 + i * 1024,
            nullptr, (__half2*)hid16, M, 1024, 256);
        gemm_tc_kernel<0><<<dim3(2, GM), 256, SMEM_BYTES>>>(
            hid16, w2_16 + (size_t)i * 1024 * 256, b2 + i * 256,
            tmp, nullptr, M, 256, 1024);

        float* lnout = (i == NUM_LAYERS - 1) ? (float*)d_out : xb;
        add_ln_kernel<<<M, 256>>>(xb, tmp, ln2_g + i * 256, ln2_b + i * 256, lnout, x16);
    }
}

// round 11
// speedup vs baseline: 3.2145x; 1.3795x over previous
#include <cuda_runtime.h>
#include <cuda_fp16.h>
#include <cuda_bf16.h>
#include <math.h>

#define NUM_LAYERS 2
#define B_SZ 2
#define S_TOTAL 13294
#define D_MODEL 256
#define NH 8
#define DH 32
#define NL 4
#define NP 4
#define DFF 1024
#define M_TOTAL (B_SZ * S_TOTAL)
#define PAD_M 26624            /* 208 * 128 */

__constant__ int c_H[4]     = {100, 50, 25, 13};
__constant__ int c_W[4]     = {100, 50, 25, 13};
__constant__ int c_start[4] = {0, 10000, 12500, 13125};

// ---------------- scratch (static device globals; no allocation) -------------
__device__ __align__(16) __half2 g_value_h[PAD_M * 128];  // value fp16 [row][128 half2]
__device__ __align__(16) __half  g_x16   [PAD_M * 256];   // fp16 copy of x (GEMM A)
__device__ __align__(16) __half2 g_msda16[PAD_M * 128];   // MSDA out fp16
__device__ __align__(16) __half  g_hid16 [PAD_M * DFF];   // FFN hidden fp16
__device__ __align__(16) float g_off  [M_TOTAL * D_MODEL];
__device__ __align__(16) float g_attn [M_TOTAL * 128];
__device__ __align__(16) float g_tmp  [M_TOTAL * D_MODEL];
__device__ __align__(16) float g_x    [M_TOTAL * D_MODEL];
__device__ float g_ref  [M_TOTAL * NL * 2];
// fp16 weights
__device__ __align__(16) __half g_wval16 [NUM_LAYERS * 256 * 256];
__device__ __align__(16) __half g_woff16 [NUM_LAYERS * 256 * 256];
__device__ __align__(16) __half g_wattn16[NUM_LAYERS * 256 * 128];
__device__ __align__(16) __half g_wout16 [NUM_LAYERS * 256 * 256];
__device__ __align__(16) __half g_w1_16  [NUM_LAYERS * 256 * 1024];
__device__ __align__(16) __half g_w2_16  [NUM_LAYERS * 1024 * 256];

// ---------------- fp32 -> fp16 conversion ------------------------------------
__global__ void cvt_kernel(const float* __restrict__ in, __half* __restrict__ out, int n)
{
    int i = (blockIdx.x * blockDim.x + threadIdx.x) * 2;
    if (i < n) {
        float2 f = *(const float2*)(in + i);
        *(__half2*)(out + i) = __floats2half2_rn(f.x, f.y);
    }
}

// ---------------- reference points ------------------------------------------
__global__ void ref_kernel(const float* __restrict__ vr, float* __restrict__ ref)
{
    int idx = blockIdx.x * blockDim.x + threadIdx.x;
    if (idx >= B_SZ * S_TOTAL) return;
    int b = idx / S_TOTAL;
    int s = idx % S_TOTAL;

    int lvl = 0, rem = s;
    while (lvl < 3 && rem >= c_H[lvl] * c_W[lvl]) { rem -= c_H[lvl] * c_W[lvl]; lvl++; }
    int W_ = c_W[lvl], H_ = c_H[lvl];
    int i = rem / W_, j = rem % W_;

    float vrx = vr[(b * NL + lvl) * 2 + 0];
    float vry = vr[(b * NL + lvl) * 2 + 1];
    float bx = (j + 0.5f) / (vrx * (float)W_);
    float by = (i + 0.5f) / (vry * (float)H_);

    #pragma unroll
    for (int l = 0; l < NL; l++) {
        float vx = vr[(b * NL + l) * 2 + 0];
        float vy = vr[(b * NL + l) * 2 + 1];
        ref[((size_t)idx * NL + l) * 2 + 0] = bx * vx;
        ref[((size_t)idx * NL + l) * 2 + 1] = by * vy;
    }
}

// ---------------- FP16 GEMM: cp.async 4-stage + ldmatrix + m16n8k16 ----------
#define LDSM_X4(r0,r1,r2,r3,addr) \
    asm volatile("ldmatrix.sync.aligned.m8n8.x4.shared.b16 {%0,%1,%2,%3}, [%4];" \
        : "=r"(r0), "=r"(r1), "=r"(r2), "=r"(r3) : "r"(addr))

#define LDSM_X4_T(r0,r1,r2,r3,addr) \
    asm volatile("ldmatrix.sync.aligned.m8n8.x4.trans.shared.b16 {%0,%1,%2,%3}, [%4];" \
        : "=r"(r0), "=r"(r1), "=r"(r2), "=r"(r3) : "r"(addr))

#define MMA_F16(c0,c1,c2,c3, a0,a1,a2,a3, b0,b1) \
    asm volatile("mma.sync.aligned.m16n8k16.row.col.f32.f16.f16.f32 " \
        "{%0,%1,%2,%3},{%4,%5,%6,%7},{%8,%9},{%0,%1,%2,%3};" \
        : "+f"(c0), "+f"(c1), "+f"(c2), "+f"(c3) \
        : "r"(a0), "r"(a1), "r"(a2), "r"(a3), "r"(b0), "r"(b1))

#define CP_ASYNC16(smem_addr, gptr) \
    asm volatile("cp.async.cg.shared.global [%0], [%1], 16;" \
        :: "r"(smem_addr), "l"(gptr))

#define CP_COMMIT() asm volatile("cp.async.commit_group;")
#define CP_WAIT(n)  asm volatile("cp.async.wait_group %0;" :: "n"(n))

#define A_STRIDE 40
#define B_STRIDE 136
#define STAGES 4
#define SMEM_BYTES (STAGES * (128 * A_STRIDE + 32 * B_STRIDE) * 2)

// OUTMODE: 0 = float out, 1 = fp16 out + relu, 2 = fp16 out
template<int OUTMODE>
__global__ __launch_bounds__(256)
void gemm_tc_kernel(const __half* __restrict__ A,
                    const __half* __restrict__ W,
                    const float* __restrict__ bias,
                    float* __restrict__ C,
                    __half2* __restrict__ Ch,
                    int M, int N, int K)
{
    extern __shared__ __align__(16) __half smem[];
    __half* AsBase = smem;
    __half* BsBase = smem + STAGES * 128 * A_STRIDE;

    const int bm = blockIdx.y * 128;
    const int bn = blockIdx.x * 128;
    const int tid  = threadIdx.x;
    const int lane = tid & 31;
    const int warp = tid >> 5;
    const int wm = (warp >> 2) * 64;
    const int wn = (warp & 3) * 32;

    const int arow = tid >> 1;
    const int aseg = (tid & 1) * 2;
    const int brow = tid >> 3;
    const int bseg = (tid & 7) * 2;

    float c[4][4][4];
    #pragma unroll
    for (int i = 0; i < 4; i++)
        #pragma unroll
        for (int j = 0; j < 4; j++)
            #pragma unroll
            for (int r = 0; r < 4; r++) c[i][j][r] = 0.f;

    const int NT = K >> 5;

    auto load_tile = [&](int stage, int k0) {
        const __half* ga = A + (size_t)(bm + arow) * K + k0 + aseg * 8;
        unsigned da = (unsigned)__cvta_generic_to_shared(
            AsBase + (stage * 128 + arow) * A_STRIDE + aseg * 8);
        CP_ASYNC16(da, ga);
        CP_ASYNC16(da + 16, ga + 8);
        const __half* gb = W + (size_t)(k0 + brow) * N + bn + bseg * 8;
        unsigned db = (unsigned)__cvta_generic_to_shared(
            BsBase + (stage * 32 + brow) * B_STRIDE + bseg * 8);
        CP_ASYNC16(db, gb);
        CP_ASYNC16(db + 16, gb + 8);
    };

    #pragma unroll
    for (int s = 0; s < STAGES - 1; s++) {
        if (s < NT) load_tile(s, s << 5);
        CP_COMMIT();
    }
    CP_WAIT(STAGES - 2);
    __syncthreads();

    for (int t = 0; t < NT; t++) {
        const int cur = t % STAGES;
        const __half* Acur = AsBase + cur * 128 * A_STRIDE;
        const __half* Bcur = BsBase + cur * 32 * B_STRIDE;

        #pragma unroll
        for (int kk = 0; kk < 32; kk += 16) {
            unsigned af[4][4], bf[4][2];
            #pragma unroll
            for (int mt = 0; mt < 4; mt++) {
                unsigned addr = (unsigned)__cvta_generic_to_shared(
                    Acur + (wm + mt * 16 + (lane & 15)) * A_STRIDE + kk + ((lane >> 4) << 3));
                LDSM_X4(af[mt][0], af[mt][1], af[mt][2], af[mt][3], addr);
            }
            #pragma unroll
            for (int ntp = 0; ntp < 2; ntp++) {
                unsigned addr = (unsigned)__cvta_generic_to_shared(
                    Bcur + (kk + (lane & 15)) * B_STRIDE + wn + ntp * 16 + ((lane >> 4) << 3));
                unsigned r0, r1, r2, r3;
                LDSM_X4_T(r0, r1, r2, r3, addr);
                bf[2 * ntp][0] = r0; bf[2 * ntp][1] = r1;
                bf[2 * ntp + 1][0] = r2; bf[2 * ntp + 1][1] = r3;
            }
            #pragma unroll
            for (int mt = 0; mt < 4; mt++)
                #pragma unroll
                for (int nt = 0; nt < 4; nt++)
                    MMA_F16(c[mt][nt][0], c[mt][nt][1], c[mt][nt][2], c[mt][nt][3],
                            af[mt][0], af[mt][1], af[mt][2], af[mt][3],
                            bf[nt][0], bf[nt][1]);
        }

        int tn = t + STAGES - 1;
        if (tn < NT) load_tile(tn % STAGES, tn << 5);
        CP_COMMIT();
        CP_WAIT(STAGES - 2);
        __syncthreads();
    }

    const int grow = lane >> 2;
    #pragma unroll
    for (int mt = 0; mt < 4; mt++) {
        int row0 = bm + wm + mt * 16 + grow;
        #pragma unroll
        for (int nt = 0; nt < 4; nt++) {
            int gn = bn + wn + nt * 8 + (lane & 3) * 2;
            float b0 = bias[gn], b1 = bias[gn + 1];
            float v0 = c[mt][nt][0] + b0;
            float v1 = c[mt][nt][1] + b1;
            float v2 = c[mt][nt][2] + b0;
            float v3 = c[mt][nt][3] + b1;
            if (OUTMODE == 1) {
                v0 = fmaxf(v0, 0.f); v1 = fmaxf(v1, 0.f);
                v2 = fmaxf(v2, 0.f); v3 = fmaxf(v3, 0.f);
            }
            if (OUTMODE >= 1) {
                if (row0 < M)
                    Ch[((size_t)row0 * N + gn) >> 1] = __floats2half2_rn(v0, v1);
                if (row0 + 8 < M)
                    Ch[((size_t)(row0 + 8) * N + gn) >> 1] = __floats2half2_rn(v2, v3);
            } else {
                if (row0 < M)
                    *(float2*)(C + (size_t)row0 * N + gn) = make_float2(v0, v1);
                if (row0 + 8 < M)
                    *(float2*)(C + (size_t)(row0 + 8) * N + gn) = make_float2(v2, v3);
            }
        }
    }
}

// ---------------- MSDA v4: 8 heads per warp, 16B gathers ---------------------
// one warp per (b, q); lane = h*4 + q ; lane covers channels [q*8, q*8+8) of head h
__global__ __launch_bounds__(256)
void msda_h_kernel(const __half2* __restrict__ value,
                   const float* __restrict__ off,
                   const float* __restrict__ attn_logits,
                   const float* __restrict__ ref,
                   __half2* __restrict__ out)
{
    constexpr int kH[4]  = {100, 50, 25, 13};
    constexpr int kW[4]  = {100, 50, 25, 13};
    constexpr int kSt[4] = {0, 10000, 12500, 13125};

    int gwarp = (blockIdx.x * blockDim.x + threadIdx.x) >> 5;
    int lane  = threadIdx.x & 31;
    if (gwarp >= B_SZ * S_TOTAL) return;

    const int bq = gwarp;
    const int b  = (bq >= S_TOTAL) ? 1 : 0;
    const int h  = lane >> 2;     // head 0..7
    const int q  = lane & 3;      // channel-octet 0..3

    // logits: samples q*4 .. q*4+3 of head h (16B aligned)
    float4 lg = __ldg((const float4*)(attn_logits + (size_t)bq * 128 + h * 16 + q * 4));
    float m = fmaxf(fmaxf(lg.x, lg.y), fmaxf(lg.z, lg.w));
    m = fmaxf(m, __shfl_xor_sync(0xffffffffu, m, 1));
    m = fmaxf(m, __shfl_xor_sync(0xffffffffu, m, 2));
    float e0 = __expf(lg.x - m), e1 = __expf(lg.y - m);
    float e2 = __expf(lg.z - m), e3 = __expf(lg.w - m);
    float ssum = e0 + e1 + e2 + e3;
    ssum += __shfl_xor_sync(0xffffffffu, ssum, 1);
    ssum += __shfl_xor_sync(0xffffffffu, ssum, 2);
    float inv = 1.f / ssum;
    float aw[4] = {e0 * inv, e1 * inv, e2 * inv, e3 * inv};

    // offsets: samples q*4 .. q*4+3 of head h, (x,y) pairs
    const float4* offp = (const float4*)(off + (size_t)bq * 256 + h * 32 + q * 8);
    float4 of0 = __ldg(offp);
    float4 of1 = __ldg(offp + 1);
    float offx[4] = {of0.x, of0.z, of1.x, of1.z};
    float offy[4] = {of0.y, of0.w, of1.y, of1.w};

    const float* refp = ref + (size_t)bq * (NL * 2);

    float2 acc[4];
    #pragma unroll
    for (int i = 0; i < 4; i++) acc[i] = make_float2(0.f, 0.f);

    #pragma unroll
    for (int l = 0; l < NL; l++) {
        const int H_ = kH[l], W_ = kW[l];
        const float fW = (float)W_, fH = (float)H_;
        const float invW = 1.f / fW, invH = 1.f / fH;
        float refx = __ldg(refp + l * 2 + 0);
        float refy = __ldg(refp + l * 2 + 1);
        // uint4 gather base: half2 offset = pos*128 + h*16 + q*4
        const uint4* vbase = (const uint4*)(value + ((size_t)(b * S_TOTAL + kSt[l])) * 128 + h * 16 + q * 4);
        const int srclane = (lane & 28) | l;   // lane holding sample l*4+p (register p)

        #pragma unroll
        for (int p = 0; p < NP; p++) {
            float w16 = __shfl_sync(0xffffffffu, aw[p],   srclane);
            float ox  = __shfl_sync(0xffffffffu, offx[p], srclane);
            float oy  = __shfl_sync(0xffffffffu, offy[p], srclane);

            float x = (refx + ox * invW) * fW - 0.5f;
            float y = (refy + oy * invH) * fH - 0.5f;
            float x0f = floorf(x), y0f = floorf(y);
            int x0 = (int)x0f, y0 = (int)y0f;
            float fx = x - x0f, fy = y - y0f;

            float mx0 = ((unsigned)x0     < (unsigned)W_) ? 1.f : 0.f;
            float mx1 = ((unsigned)(x0+1) < (unsigned)W_) ? 1.f : 0.f;
            float my0 = ((unsigned)y0     < (unsigned)H_) ? 1.f : 0.f;
            float my1 = ((unsigned)(y0+1) < (unsigned)H_) ? 1.f : 0.f;

            float gx1 = fx * mx1, gx0 = (1.f - fx) * mx0;
            float gy1 = fy * my1, gy0 = (1.f - fy) * my0;
            float w00 = gx0 * gy0 * w16, w10 = gx1 * gy0 * w16;
            float w01 = gx0 * gy1 * w16, w11 = gx1 * gy1 * w16;

            int cx0 = min(max(x0, 0), W_ - 1);
            int cx1 = min(max(x0 + 1, 0), W_ - 1);
            int cy0 = min(max(y0, 0), H_ - 1);
            int cy1 = min(max(y0 + 1, 0), H_ - 1);
            int r0 = cy0 * W_, r1 = cy1 * W_;

            uint4 u00 = __ldg(vbase + (size_t)(r0 + cx0) * 32);   // 128 half2 = 32 uint4
            uint4 u10 = __ldg(vbase + (size_t)(r0 + cx1) * 32);
            uint4 u01 = __ldg(vbase + (size_t)(r1 + cx0) * 32);
            uint4 u11 = __ldg(vbase + (size_t)(r1 + cx1) * 32);

            const unsigned* p00 = &u00.x;
            const unsigned* p10 = &u10.x;
            const unsigned* p01 = &u01.x;
            const unsigned* p11 = &u11.x;
            #pragma unroll
            for (int j = 0; j < 4; j++) {
                float2 f00 = __half22float2(*(const __half2*)&p00[j]);
                float2 f10 = __half22float2(*(const __half2*)&p10[j]);
                float2 f01 = __half22float2(*(const __half2*)&p01[j]);
                float2 f11 = __half22float2(*(const __half2*)&p11[j]);
                acc[j].x = fmaf(w00, f00.x, fmaf(w10, f10.x, fmaf(w01, f01.x, fmaf(w11, f11.x, acc[j].x))));
                acc[j].y = fmaf(w00, f00.y, fmaf(w10, f10.y, fmaf(w01, f01.y, fmaf(w11, f11.y, acc[j].y))));
            }
        }
    }

    __half2 o[4];
    #pragma unroll
    for (int j = 0; j < 4; j++) o[j] = __floats2half2_rn(acc[j].x, acc[j].y);
    *(uint4*)(out + (size_t)bq * 128 + h * 16 + q * 4) = *(uint4*)o;
}

// -------- residual add + LayerNorm: one WARP per row, fp32 + fp16 out --------
__global__ __launch_bounds__(256)
void add_ln_kernel(const float* __restrict__ xin,
                   const float* __restrict__ r,
                   const float* __restrict__ g,
                   const float* __restrict__ bt,
                   float* __restrict__ xout,
                   __half* __restrict__ xout16)
{
    int gwarp = (blockIdx.x * blockDim.x + threadIdx.x) >> 5;
    int lane  = threadIdx.x & 31;
    if (gwarp >= M_TOTAL) return;
    const size_t base = (size_t)gwarp * 256 + lane * 8;

    float4 a0 = *(const float4*)(xin + base);
    float4 a1 = *(const float4*)(xin + base + 4);
    float4 r0 = *(const float4*)(r + base);
    float4 r1 = *(const float4*)(r + base + 4);
    float v[8] = {a0.x + r0.x, a0.y + r0.y, a0.z + r0.z, a0.w + r0.w,
                  a1.x + r1.x, a1.y + r1.y, a1.z + r1.z, a1.w + r1.w};

    float s1 = 0.f, s2 = 0.f;
    #pragma unroll
    for (int i = 0; i < 8; i++) { s1 += v[i]; s2 = fmaf(v[i], v[i], s2); }
    #pragma unroll
    for (int o = 16; o > 0; o >>= 1) {
        s1 += __shfl_xor_sync(0xffffffffu, s1, o);
        s2 += __shfl_xor_sync(0xffffffffu, s2, o);
    }
    float mean = s1 * (1.f / 256.f);
    float var  = s2 * (1.f / 256.f) - mean * mean;
    float inv  = rsqrtf(var + 1e-5f);

    float4 g0 = *(const float4*)(g + lane * 8);
    float4 g1 = *(const float4*)(g + lane * 8 + 4);
    float4 b0 = *(const float4*)(bt + lane * 8);
    float4 b1 = *(const float4*)(bt + lane * 8 + 4);
    float gg[8] = {g0.x, g0.y, g0.z, g0.w, g1.x, g1.y, g1.z, g1.w};
    float bb[8] = {b0.x, b0.y, b0.z, b0.w, b1.x, b1.y, b1.z, b1.w};

    float o[8];
    #pragma unroll
    for (int i = 0; i < 8; i++) o[i] = (v[i] - mean) * inv * gg[i] + bb[i];

    *(float4*)(xout + base)     = make_float4(o[0], o[1], o[2], o[3]);
    *(float4*)(xout + base + 4) = make_float4(o[4], o[5], o[6], o[7]);
    __half2 h[4] = {__floats2half2_rn(o[0], o[1]), __floats2half2_rn(o[2], o[3]),
                    __floats2half2_rn(o[4], o[5]), __floats2half2_rn(o[6], o[7])};
    *(uint4*)(xout16 + base) = *(uint4*)h;
}

// -----------------------------------------------------------------------------
extern "C" void kernel_launch(void* const* d_in, const int* in_sizes, int n_in,
                              void* d_out, int out_size)
{
    const float* src    = (const float*)d_in[0];
    const float* vr     = (const float*)d_in[2];
    const float* W_off  = (const float*)d_in[3];
    const float* b_off  = (const float*)d_in[4];
    const float* W_attn = (const float*)d_in[5];
    const float* b_attn = (const float*)d_in[6];
    const float* W_val  = (const float*)d_in[7];
    const float* b_val  = (const float*)d_in[8];
    const float* W_out  = (const float*)d_in[9];
    const float* b_out  = (const float*)d_in[10];
    const float* ln1_g  = (const float*)d_in[11];
    const float* ln1_b  = (const float*)d_in[12];
    const float* W1     = (const float*)d_in[13];
    const float* b1     = (const float*)d_in[14];
    const float* W2     = (const float*)d_in[15];
    const float* b2     = (const float*)d_in[16];
    const float* ln2_g  = (const float*)d_in[17];
    const float* ln2_b  = (const float*)d_in[18];

    __half2 *valueh, *msda16;
    __half *x16, *hid16, *wval16, *woff16, *wattn16, *wout16, *w1_16, *w2_16;
    float *off, *attn, *tmp, *xb, *refp;
    cudaGetSymbolAddress((void**)&valueh,  g_value_h);
    cudaGetSymbolAddress((void**)&msda16,  g_msda16);
    cudaGetSymbolAddress((void**)&x16,     g_x16);
    cudaGetSymbolAddress((void**)&hid16,   g_hid16);
    cudaGetSymbolAddress((void**)&wval16,  g_wval16);
    cudaGetSymbolAddress((void**)&woff16,  g_woff16);
    cudaGetSymbolAddress((void**)&wattn16, g_wattn16);
    cudaGetSymbolAddress((void**)&wout16,  g_wout16);
    cudaGetSymbolAddress((void**)&w1_16,   g_w1_16);
    cudaGetSymbolAddress((void**)&w2_16,   g_w2_16);
    cudaGetSymbolAddress((void**)&off,   g_off);
    cudaGetSymbolAddress((void**)&attn,  g_attn);
    cudaGetSymbolAddress((void**)&tmp,   g_tmp);
    cudaGetSymbolAddress((void**)&xb,    g_x);
    cudaGetSymbolAddress((void**)&refp,  g_ref);

    cudaFuncSetAttribute(gemm_tc_kernel<0>, cudaFuncAttributeMaxDynamicSharedMemorySize, SMEM_BYTES);
    cudaFuncSetAttribute(gemm_tc_kernel<1>, cudaFuncAttributeMaxDynamicSharedMemorySize, SMEM_BYTES);
    cudaFuncSetAttribute(gemm_tc_kernel<2>, cudaFuncAttributeMaxDynamicSharedMemorySize, SMEM_BYTES);

    const int M = M_TOTAL;
    const int GM = (M + 127) / 128;   // 208

    auto cvt = [&](const float* in, __half* out, int n) {
        cvt_kernel<<<(n / 2 + 255) / 256, 256>>>(in, out, n);
    };
    cvt(W_val,  wval16,  NUM_LAYERS * 256 * 256);
    cvt(W_off,  woff16,  NUM_LAYERS * 256 * 256);
    cvt(W_attn, wattn16, NUM_LAYERS * 256 * 128);
    cvt(W_out,  wout16,  NUM_LAYERS * 256 * 256);
    cvt(W1,     w1_16,   NUM_LAYERS * 256 * 1024);
    cvt(W2,     w2_16,   NUM_LAYERS * 1024 * 256);
    cvt(src,    x16,     M * 256);

    ref_kernel<<<(M + 255) / 256, 256>>>(vr, refp);

    for (int i = 0; i < NUM_LAYERS; i++) {
        const float* xin = (i == 0) ? src : xb;   // fp32 residual source

        gemm_tc_kernel<2><<<dim3(2, GM), 256, SMEM_BYTES>>>(
            x16, wval16 + (size_t)i * 256 * 256, b_val + i * 256,
            nullptr, valueh, M, 256, 256);
        gemm_tc_kernel<0><<<dim3(2, GM), 256, SMEM_BYTES>>>(
            x16, woff16 + (size_t)i * 256 * 256, b_off + i * 256,
            off, nullptr, M, 256, 256);
        gemm_tc_kernel<0><<<dim3(1, GM), 256, SMEM_BYTES>>>(
            x16, wattn16 + (size_t)i * 256 * 128, b_attn + i * 128,
            attn, nullptr, M, 128, 256);

        msda_h_kernel<<<(M * 32 + 255) / 256, 256>>>(valueh, off, attn, refp, msda16);

        gemm_tc_kernel<0><<<dim3(2, GM), 256, SMEM_BYTES>>>(
            (const __half*)msda16, wout16 + (size_t)i * 256 * 256, b_out + i * 256,
            tmp, nullptr, M, 256, 256);
        add_ln_kernel<<<(M * 32 + 255) / 256, 256>>>(xin, tmp, ln1_g + i * 256, ln1_b + i * 256, xb, x16);

        gemm_tc_kernel<1><<<dim3(8, GM), 256, SMEM_BYTES>>>(
            x16, w1_16 + (size_t)i * 256 * 1024, b1 + i * 1024,
            nullptr, (__half2*)hid16, M, 1024, 256);
        gemm_tc_kernel<0><<<dim3(2, GM), 256, SMEM_BYTES>>>(
            hid16, w2_16 + (size_t)i * 1024 * 256, b2 + i * 256,
            tmp, nullptr, M, 256, 1024);

        float* lnout = (i == NUM_LAYERS - 1) ? (float*)d_out : xb;
        add_ln_kernel<<<(M * 32 + 255) / 256, 256>>>(xb, tmp, ln2_g + i * 256, ln2_b + i * 256, lnout, x16);
    }
}

// round 13
// speedup vs baseline: 3.2264x; 1.0037x over previous
#include <cuda_runtime.h>
#include <cuda_fp16.h>
#include <cuda_bf16.h>
#include <math.h>

#define NUM_LAYERS 2
#define B_SZ 2
#define S_TOTAL 13294
#define D_MODEL 256
#define NH 8
#define DH 32
#define NL 4
#define NP 4
#define DFF 1024
#define M_TOTAL (B_SZ * S_TOTAL)
#define PAD_M 26624            /* 208 * 128 */

__constant__ int c_H[4]     = {100, 50, 25, 13};
__constant__ int c_W[4]     = {100, 50, 25, 13};
__constant__ int c_start[4] = {0, 10000, 12500, 13125};

// ---------------- scratch (static device globals; no allocation) -------------
__device__ __align__(16) __half2 g_value_h[PAD_M * 128];  // value fp16 [row][128 half2]
__device__ __align__(16) __half  g_x16   [PAD_M * 256];   // fp16 copy of x (GEMM A)
__device__ __align__(16) __half2 g_msda16[PAD_M * 128];   // MSDA out fp16
__device__ __align__(16) __half  g_hid16 [PAD_M * DFF];   // FFN hidden fp16
__device__ __align__(16) float g_qk  [M_TOTAL * 384];     // packed [off(256) | attn(128)]
__device__ __align__(16) float g_tmp [M_TOTAL * D_MODEL];
__device__ __align__(16) float g_x   [M_TOTAL * D_MODEL];
__device__ float g_ref  [M_TOTAL * NL * 2];
// fp16 weights
__device__ __align__(16) __half g_wval16 [NUM_LAYERS * 256 * 256];
__device__ __align__(16) __half g_wqk16  [NUM_LAYERS * 256 * 384];  // packed off|attn
__device__ __align__(16) __half g_wout16 [NUM_LAYERS * 256 * 256];
__device__ __align__(16) __half g_w1_16  [NUM_LAYERS * 256 * 1024];
__device__ __align__(16) __half g_w2_16  [NUM_LAYERS * 1024 * 256];
__device__ __align__(16) float  g_bqk    [NUM_LAYERS * 384];        // packed biases

// ---------------- fused fp32->fp16 conversion + packing (ONE launch) ---------
// pair counts per segment
#define P0 65536    /* wval   */
#define P1 65536    /* woff -> packed */
#define P2 32768    /* wattn -> packed */
#define P3 65536    /* wout   */
#define P4 262144   /* w1     */
#define P5 262144   /* w2     */
#define P6 3403264  /* src -> x16 (M_TOTAL*128) */
#define P7 256      /* b_off pack (f32) */
#define P8 128      /* b_attn pack (f32) */
#define CVT_C0 (P0)
#define CVT_C1 (CVT_C0 + P1)
#define CVT_C2 (CVT_C1 + P2)
#define CVT_C3 (CVT_C2 + P3)
#define CVT_C4 (CVT_C3 + P4)
#define CVT_C5 (CVT_C4 + P5)
#define CVT_C6 (CVT_C5 + P6)
#define CVT_C7 (CVT_C6 + P7)
#define CVT_C8 (CVT_C7 + P8)

__global__ void cvt_all_kernel(const float* __restrict__ Wval, const float* __restrict__ Woff,
                               const float* __restrict__ Wattn, const float* __restrict__ Wout,
                               const float* __restrict__ W1w, const float* __restrict__ W2w,
                               const float* __restrict__ src, const float* __restrict__ boff,
                               const float* __restrict__ battn,
                               __half* __restrict__ wval16, __half* __restrict__ wqk16,
                               __half* __restrict__ wout16, __half* __restrict__ w1_16,
                               __half* __restrict__ w2_16, __half* __restrict__ x16,
                               float* __restrict__ bqk)
{
    int i = blockIdx.x * blockDim.x + threadIdx.x;   // pair index
    if (i >= CVT_C8) return;

    if (i < CVT_C0) {
        int e = i * 2;
        float2 f = *(const float2*)(Wval + e);
        *(__half2*)(wval16 + e) = __floats2half2_rn(f.x, f.y);
    } else if (i < CVT_C1) {
        int e = (i - CVT_C0) * 2;
        int l = e >> 16, rem = e & 65535, k = rem >> 8, c = rem & 255;
        float2 f = *(const float2*)(Woff + e);
        *(__half2*)(wqk16 + (size_t)l * 98304 + k * 384 + c) = __floats2half2_rn(f.x, f.y);
    } else if (i < CVT_C2) {
        int e = (i - CVT_C1) * 2;
        int l = e >> 15, rem = e & 32767, k = rem >> 7, c = rem & 127;
        float2 f = *(const float2*)(Wattn + e);
        *(__half2*)(wqk16 + (size_t)l * 98304 + k * 384 + 256 + c) = __floats2half2_rn(f.x, f.y);
    } else if (i < CVT_C3) {
        int e = (i - CVT_C2) * 2;
        float2 f = *(const float2*)(Wout + e);
        *(__half2*)(wout16 + e) = __floats2half2_rn(f.x, f.y);
    } else if (i < CVT_C4) {
        int e = (i - CVT_C3) * 2;
        float2 f = *(const float2*)(W1w + e);
        *(__half2*)(w1_16 + e) = __floats2half2_rn(f.x, f.y);
    } else if (i < CVT_C5) {
        int e = (i - CVT_C4) * 2;
        float2 f = *(const float2*)(W2w + e);
        *(__half2*)(w2_16 + e) = __floats2half2_rn(f.x, f.y);
    } else if (i < CVT_C6) {
        int e = (i - CVT_C5) * 2;
        float2 f = *(const float2*)(src + e);
        *(__half2*)(x16 + e) = __floats2half2_rn(f.x, f.y);
    } else if (i < CVT_C7) {
        int e = (i - CVT_C6) * 2;
        int l = e >> 8, c = e & 255;
        bqk[l * 384 + c]     = boff[e];
        bqk[l * 384 + c + 1] = boff[e + 1];
    } else {
        int e = (i - CVT_C7) * 2;
        int l = e >> 7, c = e & 127;
        bqk[l * 384 + 256 + c]     = battn[e];
        bqk[l * 384 + 256 + c + 1] = battn[e + 1];
    }
}

// ---------------- reference points ------------------------------------------
__global__ void ref_kernel(const float* __restrict__ vr, float* __restrict__ ref)
{
    int idx = blockIdx.x * blockDim.x + threadIdx.x;
    if (idx >= B_SZ * S_TOTAL) return;
    int b = idx / S_TOTAL;
    int s = idx % S_TOTAL;

    int lvl = 0, rem = s;
    while (lvl < 3 && rem >= c_H[lvl] * c_W[lvl]) { rem -= c_H[lvl] * c_W[lvl]; lvl++; }
    int W_ = c_W[lvl], H_ = c_H[lvl];
    int i = rem / W_, j = rem % W_;

    float vrx = vr[(b * NL + lvl) * 2 + 0];
    float vry = vr[(b * NL + lvl) * 2 + 1];
    float bx = (j + 0.5f) / (vrx * (float)W_);
    float by = (i + 0.5f) / (vry * (float)H_);

    #pragma unroll
    for (int l = 0; l < NL; l++) {
        float vx = vr[(b * NL + l) * 2 + 0];
        float vy = vr[(b * NL + l) * 2 + 1];
        ref[((size_t)idx * NL + l) * 2 + 0] = bx * vx;
        ref[((size_t)idx * NL + l) * 2 + 1] = by * vy;
    }
}

// ---------------- FP16 GEMM: cp.async 4-stage + ldmatrix + m16n8k16 ----------
#define LDSM_X4(r0,r1,r2,r3,addr) \
    asm volatile("ldmatrix.sync.aligned.m8n8.x4.shared.b16 {%0,%1,%2,%3}, [%4];" \
        : "=r"(r0), "=r"(r1), "=r"(r2), "=r"(r3) : "r"(addr))

#define LDSM_X4_T(r0,r1,r2,r3,addr) \
    asm volatile("ldmatrix.sync.aligned.m8n8.x4.trans.shared.b16 {%0,%1,%2,%3}, [%4];" \
        : "=r"(r0), "=r"(r1), "=r"(r2), "=r"(r3) : "r"(addr))

#define MMA_F16(c0,c1,c2,c3, a0,a1,a2,a3, b0,b1) \
    asm volatile("mma.sync.aligned.m16n8k16.row.col.f32.f16.f16.f32 " \
        "{%0,%1,%2,%3},{%4,%5,%6,%7},{%8,%9},{%0,%1,%2,%3};" \
        : "+f"(c0), "+f"(c1), "+f"(c2), "+f"(c3) \
        : "r"(a0), "r"(a1), "r"(a2), "r"(a3), "r"(b0), "r"(b1))

#define CP_ASYNC16(smem_addr, gptr) \
    asm volatile("cp.async.cg.shared.global [%0], [%1], 16;" \
        :: "r"(smem_addr), "l"(gptr))

#define CP_COMMIT() asm volatile("cp.async.commit_group;")
#define CP_WAIT(n)  asm volatile("cp.async.wait_group %0;" :: "n"(n))

#define A_STRIDE 40
#define B_STRIDE 136
#define STAGES 4
#define SMEM_BYTES (STAGES * (128 * A_STRIDE + 32 * B_STRIDE) * 2)

// OUTMODE: 0 = float out, 1 = fp16 out + relu, 2 = fp16 out
template<int OUTMODE>
__global__ __launch_bounds__(256)
void gemm_tc_kernel(const __half* __restrict__ A,
                    const __half* __restrict__ W,
                    const float* __restrict__ bias,
                    float* __restrict__ C,
                    __half2* __restrict__ Ch,
                    int M, int N, int K)
{
    extern __shared__ __align__(16) __half smem[];
    __half* AsBase = smem;
    __half* BsBase = smem + STAGES * 128 * A_STRIDE;

    const int bm = blockIdx.y * 128;
    const int bn = blockIdx.x * 128;
    const int tid  = threadIdx.x;
    const int lane = tid & 31;
    const int warp = tid >> 5;
    const int wm = (warp >> 2) * 64;
    const int wn = (warp & 3) * 32;

    const int arow = tid >> 1;
    const int aseg = (tid & 1) * 2;
    const int brow = tid >> 3;
    const int bseg = (tid & 7) * 2;

    float c[4][4][4];
    #pragma unroll
    for (int i = 0; i < 4; i++)
        #pragma unroll
        for (int j = 0; j < 4; j++)
            #pragma unroll
            for (int r = 0; r < 4; r++) c[i][j][r] = 0.f;

    const int NT = K >> 5;

    auto load_tile = [&](int stage, int k0) {
        const __half* ga = A + (size_t)(bm + arow) * K + k0 + aseg * 8;
        unsigned da = (unsigned)__cvta_generic_to_shared(
            AsBase + (stage * 128 + arow) * A_STRIDE + aseg * 8);
        CP_ASYNC16(da, ga);
        CP_ASYNC16(da + 16, ga + 8);
        const __half* gb = W + (size_t)(k0 + brow) * N + bn + bseg * 8;
        unsigned db = (unsigned)__cvta_generic_to_shared(
            BsBase + (stage * 32 + brow) * B_STRIDE + bseg * 8);
        CP_ASYNC16(db, gb);
        CP_ASYNC16(db + 16, gb + 8);
    };

    #pragma unroll
    for (int s = 0; s < STAGES - 1; s++) {
        if (s < NT) load_tile(s, s << 5);
        CP_COMMIT();
    }
    CP_WAIT(STAGES - 2);
    __syncthreads();

    for (int t = 0; t < NT; t++) {
        const int cur = t % STAGES;
        const __half* Acur = AsBase + cur * 128 * A_STRIDE;
        const __half* Bcur = BsBase + cur * 32 * B_STRIDE;

        // issue next tile's loads BEFORE compute (overlap DMA with MMA of tile t)
        int tn = t + STAGES - 1;
        if (tn < NT) load_tile(tn % STAGES, tn << 5);
        CP_COMMIT();

        #pragma unroll
        for (int kk = 0; kk < 32; kk += 16) {
            unsigned af[4][4], bf[4][2];
            #pragma unroll
            for (int mt = 0; mt < 4; mt++) {
                unsigned addr = (unsigned)__cvta_generic_to_shared(
                    Acur + (wm + mt * 16 + (lane & 15)) * A_STRIDE + kk + ((lane >> 4) << 3));
                LDSM_X4(af[mt][0], af[mt][1], af[mt][2], af[mt][3], addr);
            }
            #pragma unroll
            for (int ntp = 0; ntp < 2; ntp++) {
                unsigned addr = (unsigned)__cvta_generic_to_shared(
                    Bcur + (kk + (lane & 15)) * B_STRIDE + wn + ntp * 16 + ((lane >> 4) << 3));
                unsigned r0, r1, r2, r3;
                LDSM_X4_T(r0, r1, r2, r3, addr);
                bf[2 * ntp][0] = r0; bf[2 * ntp][1] = r1;
                bf[2 * ntp + 1][0] = r2; bf[2 * ntp + 1][1] = r3;
            }
            #pragma unroll
            for (int mt = 0; mt < 4; mt++)
                #pragma unroll
                for (int nt = 0; nt < 4; nt++)
                    MMA_F16(c[mt][nt][0], c[mt][nt][1], c[mt][nt][2], c[mt][nt][3],
                            af[mt][0], af[mt][1], af[mt][2], af[mt][3],
                            bf[nt][0], bf[nt][1]);
        }

        CP_WAIT(STAGES - 2);
        __syncthreads();
    }

    const int grow = lane >> 2;
    #pragma unroll
    for (int mt = 0; mt < 4; mt++) {
        int row0 = bm + wm + mt * 16 + grow;
        #pragma unroll
        for (int nt = 0; nt < 4; nt++) {
            int gn = bn + wn + nt * 8 + (lane & 3) * 2;
            float b0 = bias[gn], b1 = bias[gn + 1];
            float v0 = c[mt][nt][0] + b0;
            float v1 = c[mt][nt][1] + b1;
            float v2 = c[mt][nt][2] + b0;
            float v3 = c[mt][nt][3] + b1;
            if (OUTMODE == 1) {
                v0 = fmaxf(v0, 0.f); v1 = fmaxf(v1, 0.f);
                v2 = fmaxf(v2, 0.f); v3 = fmaxf(v3, 0.f);
            }
            if (OUTMODE >= 1) {
                if (row0 < M)
                    Ch[((size_t)row0 * N + gn) >> 1] = __floats2half2_rn(v0, v1);
                if (row0 + 8 < M)
                    Ch[((size_t)(row0 + 8) * N + gn) >> 1] = __floats2half2_rn(v2, v3);
            } else {
                if (row0 < M)
                    *(float2*)(C + (size_t)row0 * N + gn) = make_float2(v0, v1);
                if (row0 + 8 < M)
                    *(float2*)(C + (size_t)(row0 + 8) * N + gn) = make_float2(v2, v3);
            }
        }
    }
}

// ---------------- MSDA v4: 8 heads per warp, 16B gathers ---------------------
// one warp per (b, q); lane = h*4 + q ; reads packed qk buffer [off(256)|attn(128)]
__global__ __launch_bounds__(256)
void msda_h_kernel(const __half2* __restrict__ value,
                   const float* __restrict__ qk,
                   const float* __restrict__ ref,
                   __half2* __restrict__ out)
{
    constexpr int kH[4]  = {100, 50, 25, 13};
    constexpr int kW[4]  = {100, 50, 25, 13};
    constexpr int kSt[4] = {0, 10000, 12500, 13125};

    int gwarp = (blockIdx.x * blockDim.x + threadIdx.x) >> 5;
    int lane  = threadIdx.x & 31;
    if (gwarp >= B_SZ * S_TOTAL) return;

    const int bq = gwarp;
    const int b  = (bq >= S_TOTAL) ? 1 : 0;
    const int h  = lane >> 2;     // head 0..7
    const int q  = lane & 3;      // channel-octet 0..3

    // logits: samples q*4 .. q*4+3 of head h (16B aligned)
    float4 lg = __ldg((const float4*)(qk + (size_t)bq * 384 + 256 + h * 16 + q * 4));
    float m = fmaxf(fmaxf(lg.x, lg.y), fmaxf(lg.z, lg.w));
    m = fmaxf(m, __shfl_xor_sync(0xffffffffu, m, 1));
    m = fmaxf(m, __shfl_xor_sync(0xffffffffu, m, 2));
    float e0 = __expf(lg.x - m), e1 = __expf(lg.y - m);
    float e2 = __expf(lg.z - m), e3 = __expf(lg.w - m);
    float ssum = e0 + e1 + e2 + e3;
    ssum += __shfl_xor_sync(0xffffffffu, ssum, 1);
    ssum += __shfl_xor_sync(0xffffffffu, ssum, 2);
    float inv = 1.f / ssum;
    float aw[4] = {e0 * inv, e1 * inv, e2 * inv, e3 * inv};

    // offsets: samples q*4 .. q*4+3 of head h, (x,y) pairs
    const float4* offp = (const float4*)(qk + (size_t)bq * 384 + h * 32 + q * 8);
    float4 of0 = __ldg(offp);
    float4 of1 = __ldg(offp + 1);
    float offx[4] = {of0.x, of0.z, of1.x, of1.z};
    float offy[4] = {of0.y, of0.w, of1.y, of1.w};

    const float* refp = ref + (size_t)bq * (NL * 2);

    float2 acc[4];
    #pragma unroll
    for (int i = 0; i < 4; i++) acc[i] = make_float2(0.f, 0.f);

    #pragma unroll
    for (int l = 0; l < NL; l++) {
        const int H_ = kH[l], W_ = kW[l];
        const float fW = (float)W_, fH = (float)H_;
        const float invW = 1.f / fW, invH = 1.f / fH;
        float refx = __ldg(refp + l * 2 + 0);
        float refy = __ldg(refp + l * 2 + 1);
        const uint4* vbase = (const uint4*)(value + ((size_t)(b * S_TOTAL + kSt[l])) * 128 + h * 16 + q * 4);
        const int srclane = (lane & 28) | l;

        #pragma unroll
        for (int p = 0; p < NP; p++) {
            float w16 = __shfl_sync(0xffffffffu, aw[p],   srclane);
            float ox  = __shfl_sync(0xffffffffu, offx[p], srclane);
            float oy  = __shfl_sync(0xffffffffu, offy[p], srclane);

            float x = (refx + ox * invW) * fW - 0.5f;
            float y = (refy + oy * invH) * fH - 0.5f;
            float x0f = floorf(x), y0f = floorf(y);
            int x0 = (int)x0f, y0 = (int)y0f;
            float fx = x - x0f, fy = y - y0f;

            float mx0 = ((unsigned)x0     < (unsigned)W_) ? 1.f : 0.f;
            float mx1 = ((unsigned)(x0+1) < (unsigned)W_) ? 1.f : 0.f;
            float my0 = ((unsigned)y0     < (unsigned)H_) ? 1.f : 0.f;
            float my1 = ((unsigned)(y0+1) < (unsigned)H_) ? 1.f : 0.f;

            float gx1 = fx * mx1, gx0 = (1.f - fx) * mx0;
            float gy1 = fy * my1, gy0 = (1.f - fy) * my0;
            float w00 = gx0 * gy0 * w16, w10 = gx1 * gy0 * w16;
            float w01 = gx0 * gy1 * w16, w11 = gx1 * gy1 * w16;

            int cx0 = min(max(x0, 0), W_ - 1);
            int cx1 = min(max(x0 + 1, 0), W_ - 1);
            int cy0 = min(max(y0, 0), H_ - 1);
            int cy1 = min(max(y0 + 1, 0), H_ - 1);
            int r0 = cy0 * W_, r1 = cy1 * W_;

            uint4 u00 = __ldg(vbase + (size_t)(r0 + cx0) * 32);
            uint4 u10 = __ldg(vbase + (size_t)(r0 + cx1) * 32);
            uint4 u01 = __ldg(vbase + (size_t)(r1 + cx0) * 32);
            uint4 u11 = __ldg(vbase + (size_t)(r1 + cx1) * 32);

            const unsigned* p00 = &u00.x;
            const unsigned* p10 = &u10.x;
            const unsigned* p01 = &u01.x;
            const unsigned* p11 = &u11.x;
            #pragma unroll
            for (int j = 0; j < 4; j++) {
                float2 f00 = __half22float2(*(const __half2*)&p00[j]);
                float2 f10 = __half22float2(*(const __half2*)&p10[j]);
                float2 f01 = __half22float2(*(const __half2*)&p01[j]);
                float2 f11 = __half22float2(*(const __half2*)&p11[j]);
                acc[j].x = fmaf(w00, f00.x, fmaf(w10, f10.x, fmaf(w01, f01.x, fmaf(w11, f11.x, acc[j].x))));
                acc[j].y = fmaf(w00, f00.y, fmaf(w10, f10.y, fmaf(w01, f01.y, fmaf(w11, f11.y, acc[j].y))));
            }
        }
    }

    __half2 o[4];
    #pragma unroll
    for (int j = 0; j < 4; j++) o[j] = __floats2half2_rn(acc[j].x, acc[j].y);
    *(uint4*)(out + (size_t)bq * 128 + h * 16 + q * 4) = *(uint4*)o;
}

// -------- residual add + LayerNorm: one WARP per row, fp32 + fp16 out --------
__global__ __launch_bounds__(256)
void add_ln_kernel(const float* __restrict__ xin,
                   const float* __restrict__ r,
                   const float* __restrict__ g,
                   const float* __restrict__ bt,
                   float* __restrict__ xout,
                   __half* __restrict__ xout16)
{
    int gwarp = (blockIdx.x * blockDim.x + threadIdx.x) >> 5;
    int lane  = threadIdx.x & 31;
    if (gwarp >= M_TOTAL) return;
    const size_t base = (size_t)gwarp * 256 + lane * 8;

    float4 a0 = *(const float4*)(xin + base);
    float4 a1 = *(const float4*)(xin + base + 4);
    float4 r0 = *(const float4*)(r + base);
    float4 r1 = *(const float4*)(r + base + 4);
    float v[8] = {a0.x + r0.x, a0.y + r0.y, a0.z + r0.z, a0.w + r0.w,
                  a1.x + r1.x, a1.y + r1.y, a1.z + r1.z, a1.w + r1.w};

    float s1 = 0.f, s2 = 0.f;
    #pragma unroll
    for (int i = 0; i < 8; i++) { s1 += v[i]; s2 = fmaf(v[i], v[i], s2); }
    #pragma unroll
    for (int o = 16; o > 0; o >>= 1) {
        s1 += __shfl_xor_sync(0xffffffffu, s1, o);
        s2 += __shfl_xor_sync(0xffffffffu, s2, o);
    }
    float mean = s1 * (1.f / 256.f);
    float var  = s2 * (1.f / 256.f) - mean * mean;
    float inv  = rsqrtf(var + 1e-5f);

    float4 g0 = *(const float4*)(g + lane * 8);
    float4 g1 = *(const float4*)(g + lane * 8 + 4);
    float4 b0 = *(const float4*)(bt + lane * 8);
    float4 b1 = *(const float4*)(bt + lane * 8 + 4);
    float gg[8] = {g0.x, g0.y, g0.z, g0.w, g1.x, g1.y, g1.z, g1.w};
    float bb[8] = {b0.x, b0.y, b0.z, b0.w, b1.x, b1.y, b1.z, b1.w};

    float o[8];
    #pragma unroll
    for (int i = 0; i < 8; i++) o[i] = (v[i] - mean) * inv * gg[i] + bb[i];

    *(float4*)(xout + base)     = make_float4(o[0], o[1], o[2], o[3]);
    *(float4*)(xout + base + 4) = make_float4(o[4], o[5], o[6], o[7]);
    __half2 h[4] = {__floats2half2_rn(o[0], o[1]), __floats2half2_rn(o[2], o[3]),
                    __floats2half2_rn(o[4], o[5]), __floats2half2_rn(o[6], o[7])};
    *(uint4*)(xout16 + base) = *(uint4*)h;
}

// -----------------------------------------------------------------------------
extern "C" void kernel_launch(void* const* d_in, const int* in_sizes, int n_in,
                              void* d_out, int out_size)
{
    const float* src    = (const float*)d_in[0];
    const float* vr     = (const float*)d_in[2];
    const float* W_off  = (const float*)d_in[3];
    const float* b_off  = (const float*)d_in[4];
    const float* W_attn = (const float*)d_in[5];
    const float* b_attn = (const float*)d_in[6];
    const float* W_val  = (const float*)d_in[7];
    const float* b_val  = (const float*)d_in[8];
    const float* W_out  = (const float*)d_in[9];
    const float* b_out  = (const float*)d_in[10];
    const float* ln1_g  = (const float*)d_in[11];
    const float* ln1_b  = (const float*)d_in[12];
    const float* W1     = (const float*)d_in[13];
    const float* b1     = (const float*)d_in[14];
    const float* W2     = (const float*)d_in[15];
    const float* b2     = (const float*)d_in[16];
    const float* ln2_g  = (const float*)d_in[17];
    const float* ln2_b  = (const float*)d_in[18];

    __half2 *valueh, *msda16;
    __half *x16, *hid16, *wval16, *wqk16, *wout16, *w1_16, *w2_16;
    float *qk, *bqk, *tmp, *xb, *refp;
    cudaGetSymbolAddress((void**)&valueh,  g_value_h);
    cudaGetSymbolAddress((void**)&msda16,  g_msda16);
    cudaGetSymbolAddress((void**)&x16,     g_x16);
    cudaGetSymbolAddress((void**)&hid16,   g_hid16);
    cudaGetSymbolAddress((void**)&wval16,  g_wval16);
    cudaGetSymbolAddress((void**)&wqk16,   g_wqk16);
    cudaGetSymbolAddress((void**)&wout16,  g_wout16);
    cudaGetSymbolAddress((void**)&w1_16,   g_w1_16);
    cudaGetSymbolAddress((void**)&w2_16,   g_w2_16);
    cudaGetSymbolAddress((void**)&qk,    g_qk);
    cudaGetSymbolAddress((void**)&bqk,   g_bqk);
    cudaGetSymbolAddress((void**)&tmp,   g_tmp);
    cudaGetSymbolAddress((void**)&xb,    g_x);
    cudaGetSymbolAddress((void**)&refp,  g_ref);

    cudaFuncSetAttribute(gemm_tc_kernel<0>, cudaFuncAttributeMaxDynamicSharedMemorySize, SMEM_BYTES);
    cudaFuncSetAttribute(gemm_tc_kernel<1>, cudaFuncAttributeMaxDynamicSharedMemorySize, SMEM_BYTES);
    cudaFuncSetAttribute(gemm_tc_kernel<2>, cudaFuncAttributeMaxDynamicSharedMemorySize, SMEM_BYTES);

    const int M = M_TOTAL;
    const int GM = (M + 127) / 128;   // 208

    // launch 0: all conversions + packing in ONE kernel
    cvt_all_kernel<<<(CVT_C8 + 255) / 256, 256>>>(
        W_val, W_off, W_attn, W_out, W1, W2, src, b_off, b_attn,
        wval16, wqk16, wout16, w1_16, w2_16, x16, bqk);

    // launch 1
    ref_kernel<<<(M + 255) / 256, 256>>>(vr, refp);

    for (int i = 0; i < NUM_LAYERS; i++) {
        const float* xin = (i == 0) ? src : xb;   // fp32 residual source

        // value projection (fp16 out)
        gemm_tc_kernel<2><<<dim3(2, GM), 256, SMEM_BYTES>>>(
            x16, wval16 + (size_t)i * 256 * 256, b_val + i * 256,
            nullptr, valueh, M, 256, 256);
        // fused off+attn projection (N=384, f32 out)
        gemm_tc_kernel<0><<<dim3(3, GM), 256, SMEM_BYTES>>>(
            x16, wqk16 + (size_t)i * 256 * 384, bqk + i * 384,
            qk, nullptr, M, 384, 256);

        msda_h_kernel<<<(M * 32 + 255) / 256, 256>>>(valueh, qk, refp, msda16);

        gemm_tc_kernel<0><<<dim3(2, GM), 256, SMEM_BYTES>>>(
            (const __half*)msda16, wout16 + (size_t)i * 256 * 256, b_out + i * 256,
            tmp, nullptr, M, 256, 256);
        add_ln_kernel<<<(M * 32 + 255) / 256, 256>>>(xin, tmp, ln1_g + i * 256, ln1_b + i * 256, xb, x16);

        gemm_tc_kernel<1><<<dim3(8, GM), 256, SMEM_BYTES>>>(
            x16, w1_16 + (size_t)i * 256 * 1024, b1 + i * 1024,
            nullptr, (__half2*)hid16, M, 1024, 256);
        gemm_tc_kernel<0><<<dim3(2, GM), 256, SMEM_BYTES>>>(
            hid16, w2_16 + (size_t)i * 1024 * 256, b2 + i * 256,
            tmp, nullptr, M, 256, 1024);

        float* lnout = (i == NUM_LAYERS - 1) ? (float*)d_out : xb;
        add_ln_kernel<<<(M * 32 + 255) / 256, 256>>>(xb, tmp, ln2_g + i * 256, ln2_b + i * 256, lnout, x16);
    }
}